// round 1
// baseline (speedup 1.0000x reference)
#include <cuda_runtime.h>
#include <math.h>

#define NN 100000
#define RR 3
#define EE 1600000

// ---------------- scratch (static __device__, no allocations) ----------------
__device__ __align__(16) float g_Z1[RR][(long)NN * 128];   // layer1 projected feats
__device__ __align__(16) float g_EL1[RR][NN * 4];
__device__ __align__(16) float g_ER1[RR][NN * 4];
__device__ __align__(16) float g_DEN1[RR][NN * 4];
__device__ __align__(16) float g_H1[(long)NN * 128];       // accum -> elu'd hidden
__device__ __align__(16) float g_Z2[RR][NN * 16];
__device__ __align__(16) float g_EL2[RR][NN];
__device__ __align__(16) float g_ER2[RR][NN];
__device__ __align__(16) float g_DEN2[RR][NN];
__device__ __align__(16) float g_O2[NN * 16];

// vector reduction to global memory (sm_90+)
__device__ __forceinline__ void red_add_v4(float* addr, float a, float b, float c, float d) {
    asm volatile("red.global.add.v4.f32 [%0], {%1,%2,%3,%4};"
                 :: "l"(addr), "f"(a), "f"(b), "f"(c), "f"(d) : "memory");
}

__device__ __forceinline__ float lrexp(float a, float b) {
    float e = a + b;
    e = e > 0.f ? e : 0.2f * e;
    return __expf(e);
}

// ---------------- zero accumulators ----------------
__global__ void k_zero() {
    long tid = blockIdx.x * (long)blockDim.x + threadIdx.x;
    long stride = (long)gridDim.x * blockDim.x;
    float4 z4 = make_float4(0.f, 0.f, 0.f, 0.f);
    long n_h1 = (long)NN * 128 / 4;
    for (long i = tid; i < n_h1; i += stride) ((float4*)g_H1)[i] = z4;
    long n_d1 = (long)RR * NN;              // RR*NN*4 floats = RR*NN float4
    for (long i = tid; i < n_d1; i += stride) ((float4*)g_DEN1)[i] = z4;
    long n_o2 = (long)NN * 16 / 4;
    for (long i = tid; i < n_o2; i += stride) ((float4*)g_O2)[i] = z4;
    long n_d2 = (long)RR * NN;
    for (long i = tid; i < n_d2; i += stride) ((float*)g_DEN2)[i] = 0.f;
}

// ---------------- layer1 GEMM: z = x @ W1[rel], fused el/er epilogue ----------
// block = 256 threads, computes 64 rows x 128 cols. warp w owns rows w*8..w*8+7,
// lane owns cols lane*4..lane*4+3.
__global__ __launch_bounds__(256) void k_gemm1(const float* __restrict__ x,
                                               const float* __restrict__ W1,
                                               const float* __restrict__ al1,
                                               const float* __restrict__ ar1) {
    int rel = blockIdx.z;
    int row0 = blockIdx.x * 64;
    __shared__ float xs[32 * 68];    // transposed [k][row], pad 68 for alignment
    __shared__ float ws[32 * 128];
    int tid = threadIdx.x, lane = tid & 31, warp = tid >> 5;
    const float* W = W1 + (long)rel * 128 * 128;

    float acc[8][4];
#pragma unroll
    for (int r = 0; r < 8; r++)
#pragma unroll
        for (int j = 0; j < 4; j++) acc[r][j] = 0.f;

    for (int k0 = 0; k0 < 128; k0 += 32) {
#pragma unroll
        for (int i = 0; i < 2; i++) {
            int lin = tid + i * 256;          // 0..511 float4 slots of the x tile
            int r = lin >> 3, c4 = lin & 7;
            int grow = row0 + r; if (grow > NN - 1) grow = NN - 1;
            float4 v = *(const float4*)(x + (long)grow * 128 + k0 + c4 * 4);
            xs[(c4 * 4 + 0) * 68 + r] = v.x;
            xs[(c4 * 4 + 1) * 68 + r] = v.y;
            xs[(c4 * 4 + 2) * 68 + r] = v.z;
            xs[(c4 * 4 + 3) * 68 + r] = v.w;
        }
#pragma unroll
        for (int i = 0; i < 4; i++) {
            int lin = tid + i * 256;          // 0..1023 float4 slots of the W tile
            int kr = lin >> 5, c4 = lin & 31;
            *(float4*)(ws + kr * 128 + c4 * 4) =
                *(const float4*)(W + (long)(k0 + kr) * 128 + c4 * 4);
        }
        __syncthreads();
#pragma unroll
        for (int k = 0; k < 32; k++) {
            float4 b = *(const float4*)(ws + k * 128 + lane * 4);
            float4 alo = *(const float4*)(xs + k * 68 + warp * 8);
            float4 ahi = *(const float4*)(xs + k * 68 + warp * 8 + 4);
            float a[8] = {alo.x, alo.y, alo.z, alo.w, ahi.x, ahi.y, ahi.z, ahi.w};
#pragma unroll
            for (int r = 0; r < 8; r++) {
                acc[r][0] += a[r] * b.x;
                acc[r][1] += a[r] * b.y;
                acc[r][2] += a[r] * b.z;
                acc[r][3] += a[r] * b.w;
            }
        }
        __syncthreads();
    }

    // epilogue: store z, compute el/er (head = lane>>3, 8 lanes per head)
    float4 alv = *(const float4*)(al1 + rel * 128 + lane * 4);
    float4 arv = *(const float4*)(ar1 + rel * 128 + lane * 4);
    int h = lane >> 3;
#pragma unroll
    for (int r = 0; r < 8; r++) {
        int row = row0 + warp * 8 + r;
        bool ok = row < NN;
        if (ok)
            *(float4*)(&g_Z1[rel][(long)row * 128 + lane * 4]) =
                make_float4(acc[r][0], acc[r][1], acc[r][2], acc[r][3]);
        float pe = acc[r][0] * alv.x + acc[r][1] * alv.y + acc[r][2] * alv.z + acc[r][3] * alv.w;
        float pr = acc[r][0] * arv.x + acc[r][1] * arv.y + acc[r][2] * arv.z + acc[r][3] * arv.w;
#pragma unroll
        for (int off = 4; off >= 1; off >>= 1) {
            pe += __shfl_down_sync(0xffffffffu, pe, off, 8);
            pr += __shfl_down_sync(0xffffffffu, pr, off, 8);
        }
        if (ok && (lane & 7) == 0) {
            g_EL1[rel][row * 4 + h] = pe;
            g_ER1[rel][row * 4 + h] = pr;
        }
    }
}

// ---------------- layer1 edge pass 1: softmax denominators ----------------
__global__ __launch_bounds__(256) void k_den1(const int* __restrict__ src,
                                              const int* __restrict__ dst) {
    int rel = blockIdx.y;
    long e = blockIdx.x * 256L + threadIdx.x;
    if (e >= EE) return;
    int s = src[(long)rel * EE + e];
    int d = dst[(long)rel * EE + e];
    float4 el = *(const float4*)&g_EL1[rel][s * 4];
    float4 er = *(const float4*)&g_ER1[rel][d * 4];
    float p0 = lrexp(el.x, er.x);
    float p1 = lrexp(el.y, er.y);
    float p2 = lrexp(el.z, er.z);
    float p3 = lrexp(el.w, er.w);
    red_add_v4(&g_DEN1[rel][d * 4], p0, p1, p2, p3);
}

// ---------------- layer1 edge pass 2: weighted aggregation (warp/edge) ------
__global__ __launch_bounds__(256) void k_agg1(const int* __restrict__ src,
                                              const int* __restrict__ dst) {
    int rel = blockIdx.y;
    int lane = threadIdx.x & 31;
    long e = blockIdx.x * 8L + (threadIdx.x >> 5);
    if (e >= EE) return;
    int s = src[(long)rel * EE + e];
    int d = dst[(long)rel * EE + e];
    int h = lane >> 3;
    float p = lrexp(g_EL1[rel][s * 4 + h], g_ER1[rel][d * 4 + h]);
    float alpha = p / g_DEN1[rel][d * 4 + h];
    float4 z = *(const float4*)&g_Z1[rel][(long)s * 128 + lane * 4];
    red_add_v4(&g_H1[(long)d * 128 + lane * 4],
               alpha * z.x, alpha * z.y, alpha * z.z, alpha * z.w);
}

// ---------------- mean over relations + bias + ELU ----------------
__global__ void k_elu(const float* __restrict__ b1) {
    long i = blockIdx.x * 256L + threadIdx.x;
    if (i >= (long)NN * 128) return;
    int j = (int)(i & 127);
    float bs = b1[j] + b1[128 + j] + b1[256 + j];
    float v = (g_H1[i] + bs) * (1.f / 3.f);
    g_H1[i] = v > 0.f ? v : expm1f(v);
}

// ---------------- layer2 GEMM: z2 = h1 @ W2[rel], fused el2/er2 ----------
// block 256, 64 rows x 16 cols. thread: c = tid&15, row group rg = tid>>4 (4 rows).
__global__ __launch_bounds__(256) void k_gemm2(const float* __restrict__ W2,
                                               const float* __restrict__ al2,
                                               const float* __restrict__ ar2) {
    int rel = blockIdx.z;
    int row0 = blockIdx.x * 64;
    __shared__ float xs[64 * 132];   // pad 132 for bank spread + 16B alignment
    __shared__ float ws[128 * 16];
    int tid = threadIdx.x;
#pragma unroll
    for (int i = 0; i < 2; i++) {
        int lin = tid + i * 256;     // 512 float4 of W2 tile
        *(float4*)(ws + lin * 4) = *(const float4*)(W2 + (long)rel * 2048 + lin * 4);
    }
#pragma unroll
    for (int i = 0; i < 8; i++) {
        int lin = tid + i * 256;     // 2048 float4 of h1 tile
        int r = lin >> 5, c4 = lin & 31;
        int grow = row0 + r; if (grow > NN - 1) grow = NN - 1;
        *(float4*)(xs + r * 132 + c4 * 4) =
            *(const float4*)(g_H1 + (long)grow * 128 + c4 * 4);
    }
    __syncthreads();
    int c = tid & 15, rg = tid >> 4;
    float acc[4] = {0.f, 0.f, 0.f, 0.f};
#pragma unroll 8
    for (int k = 0; k < 128; k += 4) {
        float w0 = ws[(k + 0) * 16 + c];
        float w1 = ws[(k + 1) * 16 + c];
        float w2v = ws[(k + 2) * 16 + c];
        float w3 = ws[(k + 3) * 16 + c];
#pragma unroll
        for (int r = 0; r < 4; r++) {
            float4 xv = *(const float4*)(xs + (rg * 4 + r) * 132 + k);
            acc[r] += xv.x * w0 + xv.y * w1 + xv.z * w2v + xv.w * w3;
        }
    }
    float alv = al2[rel * 16 + c], arv = ar2[rel * 16 + c];
#pragma unroll
    for (int r = 0; r < 4; r++) {
        int row = row0 + rg * 4 + r;
        bool ok = row < NN;
        if (ok) g_Z2[rel][(long)row * 16 + c] = acc[r];
        float pe = acc[r] * alv, pr = acc[r] * arv;
#pragma unroll
        for (int off = 8; off >= 1; off >>= 1) {
            pe += __shfl_down_sync(0xffffffffu, pe, off, 16);
            pr += __shfl_down_sync(0xffffffffu, pr, off, 16);
        }
        if (ok && c == 0) { g_EL2[rel][row] = pe; g_ER2[rel][row] = pr; }
    }
}

// ---------------- layer2 edge passes ----------------
__global__ __launch_bounds__(256) void k_den2(const int* __restrict__ src,
                                              const int* __restrict__ dst) {
    int rel = blockIdx.y;
    long e = blockIdx.x * 256L + threadIdx.x;
    if (e >= EE) return;
    int s = src[(long)rel * EE + e];
    int d = dst[(long)rel * EE + e];
    float p = lrexp(g_EL2[rel][s], g_ER2[rel][d]);
    atomicAdd(&g_DEN2[rel][d], p);
}

__global__ __launch_bounds__(256) void k_agg2(const int* __restrict__ src,
                                              const int* __restrict__ dst) {
    int rel = blockIdx.y;
    long t = blockIdx.x * 256L + threadIdx.x;
    long e = t >> 2;
    int q = (int)(t & 3);
    if (e >= EE) return;
    int s = src[(long)rel * EE + e];
    int d = dst[(long)rel * EE + e];
    float p = lrexp(g_EL2[rel][s], g_ER2[rel][d]);
    float alpha = p / g_DEN2[rel][d];
    float4 z = *(const float4*)&g_Z2[rel][(long)s * 16 + q * 4];
    red_add_v4(&g_O2[(long)d * 16 + q * 4],
               alpha * z.x, alpha * z.y, alpha * z.z, alpha * z.w);
}

// ---------------- final mean + bias ----------------
__global__ void k_out(const float* __restrict__ b2, float* __restrict__ out) {
    long i = blockIdx.x * 256L + threadIdx.x;
    if (i >= (long)NN * 16) return;
    int c = (int)(i & 15);
    float bs = b2[c] + b2[16 + c] + b2[32 + c];
    out[i] = (g_O2[i] + bs) * (1.f / 3.f);
}

// ---------------- launcher ----------------
extern "C" void kernel_launch(void* const* d_in, const int* in_sizes, int n_in,
                              void* d_out, int out_size) {
    const float* x   = (const float*)d_in[0];
    const int*   src = (const int*)d_in[1];
    const int*   dst = (const int*)d_in[2];
    const float* W1  = (const float*)d_in[3];
    const float* al1 = (const float*)d_in[4];
    const float* ar1 = (const float*)d_in[5];
    const float* b1  = (const float*)d_in[6];
    const float* W2  = (const float*)d_in[7];
    const float* al2 = (const float*)d_in[8];
    const float* ar2 = (const float*)d_in[9];
    const float* b2  = (const float*)d_in[10];
    float* out = (float*)d_out;

    k_zero<<<2048, 256>>>();

    dim3 g1((NN + 63) / 64, 1, RR);
    k_gemm1<<<g1, 256>>>(x, W1, al1, ar1);

    dim3 gd((EE + 255) / 256, RR);
    k_den1<<<gd, 256>>>(src, dst);

    dim3 ga1((EE + 7) / 8, RR);
    k_agg1<<<ga1, 256>>>(src, dst);

    k_elu<<<((long)NN * 128 + 255) / 256, 256>>>(b1);

    k_gemm2<<<g1, 256>>>(W2, al2, ar2);

    k_den2<<<gd, 256>>>(src, dst);

    dim3 ga2(((long)EE * 4 + 255) / 256, RR);
    k_agg2<<<ga2, 256>>>(src, dst);

    k_out<<<((long)NN * 16 + 255) / 256, 256>>>(b2, out);
}

// round 3
// speedup vs baseline: 1.5698x; 1.5698x over previous
#include <cuda_runtime.h>
#include <math.h>

#define NN 100000
#define RR 3
#define EE 1600000
#define TOT (RR * NN)          // flattened (rel,node) buckets
#define SCAN_BLK 293           // ceil(TOT / 1024)

// ---------------- scratch (static __device__, no allocations) ----------------
__device__ __align__(16) float g_Z1[RR][(long)NN * 128];   // layer1 projected feats
__device__ __align__(16) float g_EL1[RR][NN * 4];
__device__ __align__(16) float g_ER1[RR][NN * 4];
__device__ __align__(16) float g_H1[(long)NN * 128];       // fused agg+elu output
__device__ __align__(16) float g_Z2[RR][NN * 16];
__device__ __align__(16) float g_EL2[RR][NN];
__device__ __align__(16) float g_ER2[RR][NN];

// CSR build
__device__ int g_cnt[TOT];
__device__ int g_off[TOT];
__device__ int g_cur[TOT];
__device__ int g_bsum[SCAN_BLK + 1];
__device__ int g_csrc[RR * EE];   // src ids sorted by (rel,dst)

__device__ __forceinline__ float lrexp(float a, float b) {
    float e = a + b;
    e = e > 0.f ? e : 0.2f * e;
    return __expf(e);
}

// ---------------- CSR build ----------------
__global__ void k_zero_cnt() {
    int i = blockIdx.x * 256 + threadIdx.x;
    if (i < TOT) g_cnt[i] = 0;
}

__global__ __launch_bounds__(256) void k_hist(const int* __restrict__ dst) {
    int rel = blockIdx.y;
    long e = blockIdx.x * 256L + threadIdx.x;
    if (e >= EE) return;
    int d = dst[(long)rel * EE + e];
    atomicAdd(&g_cnt[rel * NN + d], 1);
}

// block-level exclusive scan: 256 threads x 4 items = 1024 per block
__global__ __launch_bounds__(256) void k_scan1() {
    __shared__ int sm[256];
    int t = threadIdx.x;
    int base = blockIdx.x * 1024 + t * 4;
    int v[4];
#pragma unroll
    for (int k = 0; k < 4; k++) v[k] = (base + k < TOT) ? g_cnt[base + k] : 0;
    int tsum = v[0] + v[1] + v[2] + v[3];
    sm[t] = tsum;
    __syncthreads();
    for (int off = 1; off < 256; off <<= 1) {
        int x = (t >= off) ? sm[t - off] : 0;
        __syncthreads();
        sm[t] += x;
        __syncthreads();
    }
    int excl = sm[t] - tsum;
    int run = excl;
#pragma unroll
    for (int k = 0; k < 4; k++) {
        if (base + k < TOT) g_off[base + k] = run;
        run += v[k];
    }
    if (t == 255) g_bsum[blockIdx.x] = sm[255];
}

__global__ void k_scan2() {   // single block of 512 scans SCAN_BLK block sums
    __shared__ int sm[512];
    int t = threadIdx.x;
    sm[t] = (t < SCAN_BLK) ? g_bsum[t] : 0;
    __syncthreads();
    for (int off = 1; off < 512; off <<= 1) {
        int x = (t >= off) ? sm[t - off] : 0;
        __syncthreads();
        sm[t] += x;
        __syncthreads();
    }
    if (t < SCAN_BLK) g_bsum[t] = (t == 0) ? 0 : sm[t - 1];
}

__global__ __launch_bounds__(256) void k_scan3() {
    int t = threadIdx.x;
    int base = blockIdx.x * 1024 + t * 4;
    int add = g_bsum[blockIdx.x];
#pragma unroll
    for (int k = 0; k < 4; k++) {
        if (base + k < TOT) {
            int o = g_off[base + k] + add;
            g_off[base + k] = o;
            g_cur[base + k] = o;
        }
    }
}

__global__ __launch_bounds__(256) void k_scatter(const int* __restrict__ src,
                                                 const int* __restrict__ dst) {
    int rel = blockIdx.y;
    long e = blockIdx.x * 256L + threadIdx.x;
    if (e >= EE) return;
    int s = src[(long)rel * EE + e];
    int d = dst[(long)rel * EE + e];
    int pos = atomicAdd(&g_cur[rel * NN + d], 1);
    g_csrc[pos] = s;
}

// ---------------- layer1 GEMM: z = x @ W1[rel], fused el/er epilogue ----------
__global__ __launch_bounds__(256) void k_gemm1(const float* __restrict__ x,
                                               const float* __restrict__ W1,
                                               const float* __restrict__ al1,
                                               const float* __restrict__ ar1) {
    int rel = blockIdx.z;
    int row0 = blockIdx.x * 64;
    __shared__ float xs[32 * 68];
    __shared__ float ws[32 * 128];
    int tid = threadIdx.x, lane = tid & 31, warp = tid >> 5;
    const float* W = W1 + (long)rel * 128 * 128;

    float acc[8][4];
#pragma unroll
    for (int r = 0; r < 8; r++)
#pragma unroll
        for (int j = 0; j < 4; j++) acc[r][j] = 0.f;

    for (int k0 = 0; k0 < 128; k0 += 32) {
#pragma unroll
        for (int i = 0; i < 2; i++) {
            int lin = tid + i * 256;
            int r = lin >> 3, c4 = lin & 7;
            int grow = row0 + r; if (grow > NN - 1) grow = NN - 1;
            float4 v = *(const float4*)(x + (long)grow * 128 + k0 + c4 * 4);
            xs[(c4 * 4 + 0) * 68 + r] = v.x;
            xs[(c4 * 4 + 1) * 68 + r] = v.y;
            xs[(c4 * 4 + 2) * 68 + r] = v.z;
            xs[(c4 * 4 + 3) * 68 + r] = v.w;
        }
#pragma unroll
        for (int i = 0; i < 4; i++) {
            int lin = tid + i * 256;
            int kr = lin >> 5, c4 = lin & 31;
            *(float4*)(ws + kr * 128 + c4 * 4) =
                *(const float4*)(W + (long)(k0 + kr) * 128 + c4 * 4);
        }
        __syncthreads();
#pragma unroll
        for (int k = 0; k < 32; k++) {
            float4 b = *(const float4*)(ws + k * 128 + lane * 4);
            float4 alo = *(const float4*)(xs + k * 68 + warp * 8);
            float4 ahi = *(const float4*)(xs + k * 68 + warp * 8 + 4);
            float a[8] = {alo.x, alo.y, alo.z, alo.w, ahi.x, ahi.y, ahi.z, ahi.w};
#pragma unroll
            for (int r = 0; r < 8; r++) {
                acc[r][0] += a[r] * b.x;
                acc[r][1] += a[r] * b.y;
                acc[r][2] += a[r] * b.z;
                acc[r][3] += a[r] * b.w;
            }
        }
        __syncthreads();
    }

    float4 alv = *(const float4*)(al1 + rel * 128 + lane * 4);
    float4 arv = *(const float4*)(ar1 + rel * 128 + lane * 4);
    int h = lane >> 3;
#pragma unroll
    for (int r = 0; r < 8; r++) {
        int row = row0 + warp * 8 + r;
        bool ok = row < NN;
        if (ok)
            *(float4*)(&g_Z1[rel][(long)row * 128 + lane * 4]) =
                make_float4(acc[r][0], acc[r][1], acc[r][2], acc[r][3]);
        float pe = acc[r][0] * alv.x + acc[r][1] * alv.y + acc[r][2] * alv.z + acc[r][3] * alv.w;
        float pr = acc[r][0] * arv.x + acc[r][1] * arv.y + acc[r][2] * arv.z + acc[r][3] * arv.w;
#pragma unroll
        for (int off = 4; off >= 1; off >>= 1) {
            pe += __shfl_down_sync(0xffffffffu, pe, off, 8);
            pr += __shfl_down_sync(0xffffffffu, pr, off, 8);
        }
        if (ok && (lane & 7) == 0) {
            g_EL1[rel][row * 4 + h] = pe;
            g_ER1[rel][row * 4 + h] = pr;
        }
    }
}

// ---------------- layer1 fused CSR aggregation (warp per dst) ----------------
// softmax denom in registers, alpha-weighted z gather, mean+bias+ELU, single write.
__global__ __launch_bounds__(256) void k_agg1csr(const float* __restrict__ b1) {
    int w = (blockIdx.x * 256 + threadIdx.x) >> 5;
    if (w >= NN) return;
    int d = w;
    int lane = threadIdx.x & 31, h = lane >> 3, sub = lane & 7;
    float acc0 = 0.f, acc1 = 0.f, acc2 = 0.f, acc3 = 0.f;

#pragma unroll
    for (int rel = 0; rel < RR; rel++) {
        float er = g_ER1[rel][d * 4 + h];
        int idx = rel * NN + d;
        int base = g_off[idx], n = g_cnt[idx];
        // phase 1: denominator (8-way parallel per head)
        float ps = 0.f;
        for (int i = sub; i < n; i += 8) {
            int s = g_csrc[base + i];
            ps += lrexp(g_EL1[rel][s * 4 + h], er);
        }
        ps += __shfl_xor_sync(0xffffffffu, ps, 1);
        ps += __shfl_xor_sync(0xffffffffu, ps, 2);
        ps += __shfl_xor_sync(0xffffffffu, ps, 4);
        float rden = (n > 0) ? __frcp_rn(ps) : 0.f;
        // phase 2: weighted gather, 2-way unrolled for MLP
        int i = 0;
        for (; i + 2 <= n; i += 2) {
            int s0 = g_csrc[base + i];
            int s1 = g_csrc[base + i + 1];
            float el0 = g_EL1[rel][s0 * 4 + h];
            float el1 = g_EL1[rel][s1 * 4 + h];
            float4 z0 = *(const float4*)&g_Z1[rel][(long)s0 * 128 + lane * 4];
            float4 z1 = *(const float4*)&g_Z1[rel][(long)s1 * 128 + lane * 4];
            float a0 = lrexp(el0, er) * rden;
            float a1 = lrexp(el1, er) * rden;
            acc0 += a0 * z0.x + a1 * z1.x;
            acc1 += a0 * z0.y + a1 * z1.y;
            acc2 += a0 * z0.z + a1 * z1.z;
            acc3 += a0 * z0.w + a1 * z1.w;
        }
        if (i < n) {
            int s = g_csrc[base + i];
            float a = lrexp(g_EL1[rel][s * 4 + h], er) * rden;
            float4 z = *(const float4*)&g_Z1[rel][(long)s * 128 + lane * 4];
            acc0 += a * z.x; acc1 += a * z.y; acc2 += a * z.z; acc3 += a * z.w;
        }
    }
    // mean over relations + bias + ELU, single write
    int c = lane * 4;
    float4 bA = *(const float4*)(b1 + c);
    float4 bB = *(const float4*)(b1 + 128 + c);
    float4 bC = *(const float4*)(b1 + 256 + c);
    float v0 = (acc0 + bA.x + bB.x + bC.x) * (1.f / 3.f);
    float v1 = (acc1 + bA.y + bB.y + bC.y) * (1.f / 3.f);
    float v2 = (acc2 + bA.z + bB.z + bC.z) * (1.f / 3.f);
    float v3 = (acc3 + bA.w + bB.w + bC.w) * (1.f / 3.f);
    v0 = v0 > 0.f ? v0 : expm1f(v0);
    v1 = v1 > 0.f ? v1 : expm1f(v1);
    v2 = v2 > 0.f ? v2 : expm1f(v2);
    v3 = v3 > 0.f ? v3 : expm1f(v3);
    *(float4*)(&g_H1[(long)d * 128 + c]) = make_float4(v0, v1, v2, v3);
}

// ---------------- layer2 GEMM: z2 = h1 @ W2[rel], fused el2/er2 ----------
__global__ __launch_bounds__(256) void k_gemm2(const float* __restrict__ W2,
                                               const float* __restrict__ al2,
                                               const float* __restrict__ ar2) {
    int rel = blockIdx.z;
    int row0 = blockIdx.x * 64;
    __shared__ float xs[64 * 132];
    __shared__ float ws[128 * 16];
    int tid = threadIdx.x;
#pragma unroll
    for (int i = 0; i < 2; i++) {
        int lin = tid + i * 256;
        *(float4*)(ws + lin * 4) = *(const float4*)(W2 + (long)rel * 2048 + lin * 4);
    }
#pragma unroll
    for (int i = 0; i < 8; i++) {
        int lin = tid + i * 256;
        int r = lin >> 5, c4 = lin & 31;
        int grow = row0 + r; if (grow > NN - 1) grow = NN - 1;
        *(float4*)(xs + r * 132 + c4 * 4) =
            *(const float4*)(g_H1 + (long)grow * 128 + c4 * 4);
    }
    __syncthreads();
    int c = tid & 15, rg = tid >> 4;
    float acc[4] = {0.f, 0.f, 0.f, 0.f};
#pragma unroll 8
    for (int k = 0; k < 128; k += 4) {
        float w0 = ws[(k + 0) * 16 + c];
        float w1 = ws[(k + 1) * 16 + c];
        float w2v = ws[(k + 2) * 16 + c];
        float w3 = ws[(k + 3) * 16 + c];
#pragma unroll
        for (int r = 0; r < 4; r++) {
            float4 xv = *(const float4*)(xs + (rg * 4 + r) * 132 + k);
            acc[r] += xv.x * w0 + xv.y * w1 + xv.z * w2v + xv.w * w3;
        }
    }
    float alv = al2[rel * 16 + c], arv = ar2[rel * 16 + c];
#pragma unroll
    for (int r = 0; r < 4; r++) {
        int row = row0 + rg * 4 + r;
        bool ok = row < NN;
        if (ok) g_Z2[rel][(long)row * 16 + c] = acc[r];
        float pe = acc[r] * alv, pr = acc[r] * arv;
#pragma unroll
        for (int off = 8; off >= 1; off >>= 1) {
            pe += __shfl_down_sync(0xffffffffu, pe, off, 16);
            pr += __shfl_down_sync(0xffffffffu, pr, off, 16);
        }
        if (ok && c == 0) { g_EL2[rel][row] = pe; g_ER2[rel][row] = pr; }
    }
}

// ---------------- layer2 fused CSR aggregation (warp per dst) ----------------
__global__ __launch_bounds__(256) void k_agg2csr(const float* __restrict__ b2,
                                                 float* __restrict__ out) {
    int w = (blockIdx.x * 256 + threadIdx.x) >> 5;
    if (w >= NN) return;
    int d = w;
    int lane = threadIdx.x & 31, half = lane >> 4, c = lane & 15;
    float acc = 0.f;

#pragma unroll
    for (int rel = 0; rel < RR; rel++) {
        float er = g_ER2[rel][d];
        int idx = rel * NN + d;
        int base = g_off[idx], n = g_cnt[idx];
        // denominator: full-warp strided
        float ps = 0.f;
        for (int i = lane; i < n; i += 32)
            ps += lrexp(g_EL2[rel][g_csrc[base + i]], er);
        ps += __shfl_xor_sync(0xffffffffu, ps, 16);
        ps += __shfl_xor_sync(0xffffffffu, ps, 8);
        ps += __shfl_xor_sync(0xffffffffu, ps, 4);
        ps += __shfl_xor_sync(0xffffffffu, ps, 2);
        ps += __shfl_xor_sync(0xffffffffu, ps, 1);
        float rden = (n > 0) ? __frcp_rn(ps) : 0.f;
        // weighted gather: 2 edges per iteration (half-warp each)
        for (int i = half; i < n; i += 2) {
            int s = g_csrc[base + i];
            float a = lrexp(g_EL2[rel][s], er) * rden;
            acc += a * g_Z2[rel][s * 16 + c];
        }
    }
    acc += __shfl_xor_sync(0xffffffffu, acc, 16);
    if (half == 0) {
        float bs = b2[c] + b2[16 + c] + b2[32 + c];
        out[d * 16 + c] = (acc + bs) * (1.f / 3.f);
    }
}

// ---------------- launcher ----------------
extern "C" void kernel_launch(void* const* d_in, const int* in_sizes, int n_in,
                              void* d_out, int out_size) {
    const float* x   = (const float*)d_in[0];
    const int*   src = (const int*)d_in[1];
    const int*   dst = (const int*)d_in[2];
    const float* W1  = (const float*)d_in[3];
    const float* al1 = (const float*)d_in[4];
    const float* ar1 = (const float*)d_in[5];
    const float* b1  = (const float*)d_in[6];
    const float* W2  = (const float*)d_in[7];
    const float* al2 = (const float*)d_in[8];
    const float* ar2 = (const float*)d_in[9];
    const float* b2  = (const float*)d_in[10];
    float* out = (float*)d_out;

    // CSR build (counting sort of edges by (rel,dst))
    k_zero_cnt<<<(TOT + 255) / 256, 256>>>();
    dim3 ge((EE + 255) / 256, RR);
    k_hist<<<ge, 256>>>(dst);
    k_scan1<<<SCAN_BLK, 256>>>();
    k_scan2<<<1, 512>>>();
    k_scan3<<<SCAN_BLK, 256>>>();
    k_scatter<<<ge, 256>>>(src, dst);

    // layer 1
    dim3 g1((NN + 63) / 64, 1, RR);
    k_gemm1<<<g1, 256>>>(x, W1, al1, ar1);
    k_agg1csr<<<(NN * 32 + 255) / 256, 256>>>(b1);

    // layer 2
    k_gemm2<<<g1, 256>>>(W2, al2, ar2);
    k_agg2csr<<<(NN * 32 + 255) / 256, 256>>>(b2, out);
}

// round 4
// speedup vs baseline: 1.8575x; 1.1833x over previous
#include <cuda_runtime.h>
#include <cuda_fp16.h>
#include <math.h>

#define NN 100000
#define RR 3
#define EE 1600000
#define TOT (RR * NN)          // flattened (rel,node) buckets
#define SCAN_BLK 293           // ceil(TOT / 1024)

// ---------------- scratch (static __device__, no allocations) ----------------
__device__ __align__(16) __half2 g_Z1h[RR][(long)NN * 64]; // layer1 z in fp16 (77MB)
__device__ __align__(16) float g_EL1[RR][NN * 4];
__device__ __align__(16) float g_ER1[RR][NN * 4];
__device__ __align__(16) float g_H1[(long)NN * 128];       // fused agg+elu output
__device__ __align__(16) float g_Z2[RR][NN * 16];
__device__ __align__(16) float g_EL2[RR][NN];
__device__ __align__(16) float g_ER2[RR][NN];

// CSR build
__device__ int g_cnt[TOT];
__device__ int g_off[TOT];
__device__ int g_cur[TOT];
__device__ int g_bsum[SCAN_BLK + 1];
__device__ int g_csrc[RR * EE];   // src ids sorted by (rel,dst)

struct __align__(8) h4 { __half2 a, b; };

__device__ __forceinline__ float lrexp(float a, float b) {
    float e = a + b;
    e = e > 0.f ? e : 0.2f * e;
    return __expf(e);
}

// ---------------- CSR build ----------------
__global__ void k_zero_cnt() {
    int i = blockIdx.x * 256 + threadIdx.x;
    if (i < TOT) g_cnt[i] = 0;
}

__global__ __launch_bounds__(256) void k_hist(const int* __restrict__ dst) {
    int rel = blockIdx.y;
    long e = blockIdx.x * 256L + threadIdx.x;
    if (e >= EE) return;
    int d = dst[(long)rel * EE + e];
    atomicAdd(&g_cnt[rel * NN + d], 1);
}

__global__ __launch_bounds__(256) void k_scan1() {
    __shared__ int sm[256];
    int t = threadIdx.x;
    int base = blockIdx.x * 1024 + t * 4;
    int v[4];
#pragma unroll
    for (int k = 0; k < 4; k++) v[k] = (base + k < TOT) ? g_cnt[base + k] : 0;
    int tsum = v[0] + v[1] + v[2] + v[3];
    sm[t] = tsum;
    __syncthreads();
    for (int off = 1; off < 256; off <<= 1) {
        int x = (t >= off) ? sm[t - off] : 0;
        __syncthreads();
        sm[t] += x;
        __syncthreads();
    }
    int excl = sm[t] - tsum;
    int run = excl;
#pragma unroll
    for (int k = 0; k < 4; k++) {
        if (base + k < TOT) g_off[base + k] = run;
        run += v[k];
    }
    if (t == 255) g_bsum[blockIdx.x] = sm[255];
}

__global__ void k_scan2() {
    __shared__ int sm[512];
    int t = threadIdx.x;
    sm[t] = (t < SCAN_BLK) ? g_bsum[t] : 0;
    __syncthreads();
    for (int off = 1; off < 512; off <<= 1) {
        int x = (t >= off) ? sm[t - off] : 0;
        __syncthreads();
        sm[t] += x;
        __syncthreads();
    }
    if (t < SCAN_BLK) g_bsum[t] = (t == 0) ? 0 : sm[t - 1];
}

__global__ __launch_bounds__(256) void k_scan3() {
    int t = threadIdx.x;
    int base = blockIdx.x * 1024 + t * 4;
    int add = g_bsum[blockIdx.x];
#pragma unroll
    for (int k = 0; k < 4; k++) {
        if (base + k < TOT) {
            int o = g_off[base + k] + add;
            g_off[base + k] = o;
            g_cur[base + k] = o;
        }
    }
}

__global__ __launch_bounds__(256) void k_scatter(const int* __restrict__ src,
                                                 const int* __restrict__ dst) {
    int rel = blockIdx.y;
    long e = blockIdx.x * 256L + threadIdx.x;
    if (e >= EE) return;
    int s = src[(long)rel * EE + e];
    int d = dst[(long)rel * EE + e];
    int pos = atomicAdd(&g_cur[rel * NN + d], 1);
    g_csrc[pos] = s;
}

// ---------------- layer1 GEMM: z = x @ W1[rel], fused el/er, fp16 z out ------
__global__ __launch_bounds__(256) void k_gemm1(const float* __restrict__ x,
                                               const float* __restrict__ W1,
                                               const float* __restrict__ al1,
                                               const float* __restrict__ ar1) {
    int rel = blockIdx.z;
    int row0 = blockIdx.x * 64;
    __shared__ float xs[32 * 68];
    __shared__ float ws[32 * 128];
    int tid = threadIdx.x, lane = tid & 31, warp = tid >> 5;
    const float* W = W1 + (long)rel * 128 * 128;

    float acc[8][4];
#pragma unroll
    for (int r = 0; r < 8; r++)
#pragma unroll
        for (int j = 0; j < 4; j++) acc[r][j] = 0.f;

    for (int k0 = 0; k0 < 128; k0 += 32) {
#pragma unroll
        for (int i = 0; i < 2; i++) {
            int lin = tid + i * 256;
            int r = lin >> 3, c4 = lin & 7;
            int grow = row0 + r; if (grow > NN - 1) grow = NN - 1;
            float4 v = *(const float4*)(x + (long)grow * 128 + k0 + c4 * 4);
            xs[(c4 * 4 + 0) * 68 + r] = v.x;
            xs[(c4 * 4 + 1) * 68 + r] = v.y;
            xs[(c4 * 4 + 2) * 68 + r] = v.z;
            xs[(c4 * 4 + 3) * 68 + r] = v.w;
        }
#pragma unroll
        for (int i = 0; i < 4; i++) {
            int lin = tid + i * 256;
            int kr = lin >> 5, c4 = lin & 31;
            *(float4*)(ws + kr * 128 + c4 * 4) =
                *(const float4*)(W + (long)(k0 + kr) * 128 + c4 * 4);
        }
        __syncthreads();
#pragma unroll
        for (int k = 0; k < 32; k++) {
            float4 b = *(const float4*)(ws + k * 128 + lane * 4);
            float4 alo = *(const float4*)(xs + k * 68 + warp * 8);
            float4 ahi = *(const float4*)(xs + k * 68 + warp * 8 + 4);
            float a[8] = {alo.x, alo.y, alo.z, alo.w, ahi.x, ahi.y, ahi.z, ahi.w};
#pragma unroll
            for (int r = 0; r < 8; r++) {
                acc[r][0] += a[r] * b.x;
                acc[r][1] += a[r] * b.y;
                acc[r][2] += a[r] * b.z;
                acc[r][3] += a[r] * b.w;
            }
        }
        __syncthreads();
    }

    float4 alv = *(const float4*)(al1 + rel * 128 + lane * 4);
    float4 arv = *(const float4*)(ar1 + rel * 128 + lane * 4);
    int h = lane >> 3;
#pragma unroll
    for (int r = 0; r < 8; r++) {
        int row = row0 + warp * 8 + r;
        bool ok = row < NN;
        if (ok) {
            h4 hv;
            hv.a = __floats2half2_rn(acc[r][0], acc[r][1]);
            hv.b = __floats2half2_rn(acc[r][2], acc[r][3]);
            *(h4*)(&g_Z1h[rel][(long)row * 64 + lane * 2]) = hv;
        }
        float pe = acc[r][0] * alv.x + acc[r][1] * alv.y + acc[r][2] * alv.z + acc[r][3] * alv.w;
        float pr = acc[r][0] * arv.x + acc[r][1] * arv.y + acc[r][2] * arv.z + acc[r][3] * arv.w;
#pragma unroll
        for (int off = 4; off >= 1; off >>= 1) {
            pe += __shfl_down_sync(0xffffffffu, pe, off, 8);
            pr += __shfl_down_sync(0xffffffffu, pr, off, 8);
        }
        if (ok && (lane & 7) == 0) {
            g_EL1[rel][row * 4 + h] = pe;
            g_ER1[rel][row * 4 + h] = pr;
        }
    }
}

// ---------------- layer1 fused CSR aggregation (warp per dst, single pass) ---
// out_rel = (sum_i p_i z_i) / (sum_i p_i); numerator+denominator in one sweep.
__global__ __launch_bounds__(256) void k_agg1csr(const float* __restrict__ b1) {
    int w = (blockIdx.x * 256 + threadIdx.x) >> 5;
    if (w >= NN) return;
    int d = w;
    int lane = threadIdx.x & 31, h = lane >> 3;
    float acc0 = 0.f, acc1 = 0.f, acc2 = 0.f, acc3 = 0.f;

#pragma unroll
    for (int rel = 0; rel < RR; rel++) {
        float er = g_ER1[rel][d * 4 + h];
        int idx = rel * NN + d;
        int base = g_off[idx], n = g_cnt[idx];
        float a0 = 0.f, a1 = 0.f, a2 = 0.f, a3 = 0.f, den = 0.f;
        int i = 0;
        for (; i + 2 <= n; i += 2) {
            int s0 = g_csrc[base + i];
            int s1 = g_csrc[base + i + 1];
            float el0 = g_EL1[rel][s0 * 4 + h];
            float el1 = g_EL1[rel][s1 * 4 + h];
            h4 z0 = *(const h4*)&g_Z1h[rel][(long)s0 * 64 + lane * 2];
            h4 z1 = *(const h4*)&g_Z1h[rel][(long)s1 * 64 + lane * 2];
            float p0 = lrexp(el0, er);
            float p1 = lrexp(el1, er);
            float2 z0lo = __half22float2(z0.a), z0hi = __half22float2(z0.b);
            float2 z1lo = __half22float2(z1.a), z1hi = __half22float2(z1.b);
            a0 += p0 * z0lo.x + p1 * z1lo.x;
            a1 += p0 * z0lo.y + p1 * z1lo.y;
            a2 += p0 * z0hi.x + p1 * z1hi.x;
            a3 += p0 * z0hi.y + p1 * z1hi.y;
            den += p0 + p1;
        }
        if (i < n) {
            int s = g_csrc[base + i];
            float p = lrexp(g_EL1[rel][s * 4 + h], er);
            h4 z = *(const h4*)&g_Z1h[rel][(long)s * 64 + lane * 2];
            float2 zlo = __half22float2(z.a), zhi = __half22float2(z.b);
            a0 += p * zlo.x; a1 += p * zlo.y; a2 += p * zhi.x; a3 += p * zhi.y;
            den += p;
        }
        float rden = (n > 0) ? __frcp_rn(den) : 0.f;
        acc0 += a0 * rden; acc1 += a1 * rden; acc2 += a2 * rden; acc3 += a3 * rden;
    }
    // mean over relations + bias + ELU, single write
    int c = lane * 4;
    float4 bA = *(const float4*)(b1 + c);
    float4 bB = *(const float4*)(b1 + 128 + c);
    float4 bC = *(const float4*)(b1 + 256 + c);
    float v0 = (acc0 + bA.x + bB.x + bC.x) * (1.f / 3.f);
    float v1 = (acc1 + bA.y + bB.y + bC.y) * (1.f / 3.f);
    float v2 = (acc2 + bA.z + bB.z + bC.z) * (1.f / 3.f);
    float v3 = (acc3 + bA.w + bB.w + bC.w) * (1.f / 3.f);
    v0 = v0 > 0.f ? v0 : expm1f(v0);
    v1 = v1 > 0.f ? v1 : expm1f(v1);
    v2 = v2 > 0.f ? v2 : expm1f(v2);
    v3 = v3 > 0.f ? v3 : expm1f(v3);
    *(float4*)(&g_H1[(long)d * 128 + c]) = make_float4(v0, v1, v2, v3);
}

// ---------------- layer2 GEMM: z2 = h1 @ W2[rel], fused el2/er2 ----------
__global__ __launch_bounds__(256) void k_gemm2(const float* __restrict__ W2,
                                               const float* __restrict__ al2,
                                               const float* __restrict__ ar2) {
    int rel = blockIdx.z;
    int row0 = blockIdx.x * 64;
    __shared__ float xs[64 * 132];
    __shared__ float ws[128 * 16];
    int tid = threadIdx.x;
#pragma unroll
    for (int i = 0; i < 2; i++) {
        int lin = tid + i * 256;
        *(float4*)(ws + lin * 4) = *(const float4*)(W2 + (long)rel * 2048 + lin * 4);
    }
#pragma unroll
    for (int i = 0; i < 8; i++) {
        int lin = tid + i * 256;
        int r = lin >> 5, c4 = lin & 31;
        int grow = row0 + r; if (grow > NN - 1) grow = NN - 1;
        *(float4*)(xs + r * 132 + c4 * 4) =
            *(const float4*)(g_H1 + (long)grow * 128 + c4 * 4);
    }
    __syncthreads();
    int c = tid & 15, rg = tid >> 4;
    float acc[4] = {0.f, 0.f, 0.f, 0.f};
#pragma unroll 8
    for (int k = 0; k < 128; k += 4) {
        float w0 = ws[(k + 0) * 16 + c];
        float w1 = ws[(k + 1) * 16 + c];
        float w2v = ws[(k + 2) * 16 + c];
        float w3 = ws[(k + 3) * 16 + c];
#pragma unroll
        for (int r = 0; r < 4; r++) {
            float4 xv = *(const float4*)(xs + (rg * 4 + r) * 132 + k);
            acc[r] += xv.x * w0 + xv.y * w1 + xv.z * w2v + xv.w * w3;
        }
    }
    float alv = al2[rel * 16 + c], arv = ar2[rel * 16 + c];
#pragma unroll
    for (int r = 0; r < 4; r++) {
        int row = row0 + rg * 4 + r;
        bool ok = row < NN;
        if (ok) g_Z2[rel][(long)row * 16 + c] = acc[r];
        float pe = acc[r] * alv, pr = acc[r] * arv;
#pragma unroll
        for (int off = 8; off >= 1; off >>= 1) {
            pe += __shfl_down_sync(0xffffffffu, pe, off, 16);
            pr += __shfl_down_sync(0xffffffffu, pr, off, 16);
        }
        if (ok && c == 0) { g_EL2[rel][row] = pe; g_ER2[rel][row] = pr; }
    }
}

// ---------------- layer2 fused CSR aggregation (warp per dst, single pass) ---
__global__ __launch_bounds__(256) void k_agg2csr(const float* __restrict__ b2,
                                                 float* __restrict__ out) {
    int w = (blockIdx.x * 256 + threadIdx.x) >> 5;
    if (w >= NN) return;
    int d = w;
    int lane = threadIdx.x & 31, half = lane >> 4, c = lane & 15;
    float acc = 0.f;

#pragma unroll
    for (int rel = 0; rel < RR; rel++) {
        float er = g_ER2[rel][d];
        int idx = rel * NN + d;
        int base = g_off[idx], n = g_cnt[idx];
        float aR = 0.f, den = 0.f;
        // half-warp per edge: half 0 takes even i, half 1 odd i
        for (int i = half; i < n; i += 2) {
            int s = g_csrc[base + i];
            float p = lrexp(g_EL2[rel][s], er);
            aR += p * g_Z2[rel][s * 16 + c];
            den += p;
        }
        den += __shfl_xor_sync(0xffffffffu, den, 16);
        float rden = (n > 0) ? __frcp_rn(den) : 0.f;
        acc += aR * rden;
    }
    acc += __shfl_xor_sync(0xffffffffu, acc, 16);
    if (half == 0) {
        float bs = b2[c] + b2[16 + c] + b2[32 + c];
        out[d * 16 + c] = (acc + bs) * (1.f / 3.f);
    }
}

// ---------------- launcher ----------------
extern "C" void kernel_launch(void* const* d_in, const int* in_sizes, int n_in,
                              void* d_out, int out_size) {
    const float* x   = (const float*)d_in[0];
    const int*   src = (const int*)d_in[1];
    const int*   dst = (const int*)d_in[2];
    const float* W1  = (const float*)d_in[3];
    const float* al1 = (const float*)d_in[4];
    const float* ar1 = (const float*)d_in[5];
    const float* b1  = (const float*)d_in[6];
    const float* W2  = (const float*)d_in[7];
    const float* al2 = (const float*)d_in[8];
    const float* ar2 = (const float*)d_in[9];
    const float* b2  = (const float*)d_in[10];
    float* out = (float*)d_out;

    // CSR build (counting sort of edges by (rel,dst))
    k_zero_cnt<<<(TOT + 255) / 256, 256>>>();
    dim3 ge((EE + 255) / 256, RR);
    k_hist<<<ge, 256>>>(dst);
    k_scan1<<<SCAN_BLK, 256>>>();
    k_scan2<<<1, 512>>>();
    k_scan3<<<SCAN_BLK, 256>>>();
    k_scatter<<<ge, 256>>>(src, dst);

    // layer 1
    dim3 g1((NN + 63) / 64, 1, RR);
    k_gemm1<<<g1, 256>>>(x, W1, al1, ar1);
    k_agg1csr<<<(NN * 32 + 255) / 256, 256>>>(b1);

    // layer 2
    k_gemm2<<<g1, 256>>>(W2, al2, ar2);
    k_agg2csr<<<(NN * 32 + 255) / 256, 256>>>(b2, out);
}

// round 8
// speedup vs baseline: 2.1917x; 1.1799x over previous
#include <cuda_runtime.h>
#include <cuda_fp16.h>
#include <mma.h>
#include <math.h>

using namespace nvcuda;

#define NN 100000
#define RR 3
#define EE 1600000
#define TOT (RR * NN)
#define SCAN_BLK 293

__device__ __align__(16) __half2 g_Z1h[RR][(long)NN * 64];
__device__ __align__(16) float g_EL1[RR][NN * 4];
__device__ __align__(16) float g_ER1[RR][NN * 4];
__device__ __align__(16) float g_H1[(long)NN * 128];
__device__ __align__(16) float g_Z2[RR][NN * 16];
__device__ __align__(16) float g_EL2[RR][NN];
__device__ __align__(16) float g_ER2[RR][NN];

__device__ int g_cnt[TOT];
__device__ int g_off[TOT];
__device__ int g_cur[TOT];
__device__ int g_bsum[SCAN_BLK + 1];
__device__ int g_csrc[RR * EE];

struct __align__(8) h4 { __half2 a, b; };

__device__ __forceinline__ float lrexp(float a, float b) {
    float e = a + b;
    e = e > 0.f ? e : 0.2f * e;
    return __expf(e);
}

// ---------------- CSR build (verbatim from the passing R4 kernel) ------------
__global__ void k_zero_cnt() {
    int i = blockIdx.x * 256 + threadIdx.x;
    if (i < TOT) g_cnt[i] = 0;
}

__global__ __launch_bounds__(256) void k_hist(const int* __restrict__ dst) {
    int rel = blockIdx.y;
    long e = blockIdx.x * 256L + threadIdx.x;
    if (e >= EE) return;
    int d = dst[(long)rel * EE + e];
    atomicAdd(&g_cnt[rel * NN + d], 1);
}

__global__ __launch_bounds__(256) void k_scan1() {
    __shared__ int sm[256];
    int t = threadIdx.x;
    int base = blockIdx.x * 1024 + t * 4;
    int v[4];
#pragma unroll
    for (int k = 0; k < 4; k++) v[k] = (base + k < TOT) ? g_cnt[base + k] : 0;
    int tsum = v[0] + v[1] + v[2] + v[3];
    sm[t] = tsum;
    __syncthreads();
    for (int off = 1; off < 256; off <<= 1) {
        int x = (t >= off) ? sm[t - off] : 0;
        __syncthreads();
        sm[t] += x;
        __syncthreads();
    }
    int run = sm[t] - tsum;
#pragma unroll
    for (int k = 0; k < 4; k++) {
        if (base + k < TOT) g_off[base + k] = run;
        run += v[k];
    }
    if (t == 255) g_bsum[blockIdx.x] = sm[255];
}

__global__ void k_scan2() {
    __shared__ int sm[512];
    int t = threadIdx.x;
    sm[t] = (t < SCAN_BLK) ? g_bsum[t] : 0;
    __syncthreads();
    for (int off = 1; off < 512; off <<= 1) {
        int x = (t >= off) ? sm[t - off] : 0;
        __syncthreads();
        sm[t] += x;
        __syncthreads();
    }
    if (t < SCAN_BLK) g_bsum[t] = (t == 0) ? 0 : sm[t - 1];
}

__global__ __launch_bounds__(256) void k_scan3() {
    int t = threadIdx.x;
    int base = blockIdx.x * 1024 + t * 4;
    int add = g_bsum[blockIdx.x];
#pragma unroll
    for (int k = 0; k < 4; k++) {
        if (base + k < TOT) {
            int o = g_off[base + k] + add;
            g_off[base + k] = o;
            g_cur[base + k] = o;
        }
    }
}

__global__ __launch_bounds__(256) void k_scatter(const int* __restrict__ src,
                                                 const int* __restrict__ dst) {
    int rel = blockIdx.y;
    long e = blockIdx.x * 256L + threadIdx.x;
    if (e >= EE) return;
    int s = src[(long)rel * EE + e];
    int d = dst[(long)rel * EE + e];
    int pos = atomicAdd(&g_cur[rel * NN + d], 1);
    g_csrc[pos] = s;
}

// ---------------- layer1 GEMM on tensor cores via wmma -----------------------
// 128x128 tile per CTA, 8 warps (4m x 2n), K=128 in two 64-wide smem stages.
// Accumulators staged via per-warp float scratch -> fp16 tile in smem ->
// coalesced z store; el/er computed from the staged fp16 tile.
#define ASTR 72
#define BSTR 136
#define SSTR 136
__global__ __launch_bounds__(256) void k_gemm1_wmma(const float* __restrict__ x,
                                                    const float* __restrict__ W1,
                                                    const float* __restrict__ al1,
                                                    const float* __restrict__ ar1) {
    __shared__ __align__(16) char smraw[43008];
    __shared__ float alS[128];
    __shared__ float arS[128];
    __half* As = (__half*)smraw;                  // 128*72 halves = 18432 B
    __half* Bs = (__half*)(smraw + 18432);        // 64*136 halves = 17408 B
    int rel = blockIdx.z;
    int row0 = blockIdx.x * 128;
    int tid = threadIdx.x;
    int lane = tid & 31;
    int warp = tid >> 5;
    int mw = warp & 3;
    int nw = warp >> 2;
    const float* Wp = W1 + (long)rel * 16384;

    if (tid < 128) {
        alS[tid] = al1[rel * 128 + tid];
        arS[tid] = ar1[rel * 128 + tid];
    }

    wmma::fragment<wmma::accumulator, 16, 16, 16, float> acc0[4];
    wmma::fragment<wmma::accumulator, 16, 16, 16, float> acc1[4];
#pragma unroll
    for (int nt = 0; nt < 4; nt++) {
        wmma::fill_fragment(acc0[nt], 0.f);
        wmma::fill_fragment(acc1[nt], 0.f);
    }

    for (int kh = 0; kh < 2; kh++) {
        if (kh) __syncthreads();
        // A tile: 128 rows x 64 cols, fp32 -> fp16
#pragma unroll
        for (int i = 0; i < 8; i++) {
            int lin = tid + i * 256;
            int r = lin >> 4;
            int c4 = lin & 15;
            int gr = row0 + r;
            if (gr >= NN) gr = NN - 1;
            float4 v = *(const float4*)(x + (long)gr * 128 + kh * 64 + c4 * 4);
            __half2* p = (__half2*)(As + r * ASTR + c4 * 4);
            p[0] = __floats2half2_rn(v.x, v.y);
            p[1] = __floats2half2_rn(v.z, v.w);
        }
        // B tile: 64 k-rows x 128 n-cols, fp32 -> fp16
#pragma unroll
        for (int i = 0; i < 8; i++) {
            int lin = tid + i * 256;
            int r = lin >> 5;
            int c4 = lin & 31;
            float4 v = *(const float4*)(Wp + (long)(kh * 64 + r) * 128 + c4 * 4);
            __half2* p = (__half2*)(Bs + r * BSTR + c4 * 4);
            p[0] = __floats2half2_rn(v.x, v.y);
            p[1] = __floats2half2_rn(v.z, v.w);
        }
        __syncthreads();
#pragma unroll
        for (int ks = 0; ks < 4; ks++) {
            int k0 = ks * 16;
            wmma::fragment<wmma::matrix_a, 16, 16, 16, __half, wmma::row_major> af0;
            wmma::fragment<wmma::matrix_a, 16, 16, 16, __half, wmma::row_major> af1;
            wmma::load_matrix_sync(af0, As + (mw * 32) * ASTR + k0, ASTR);
            wmma::load_matrix_sync(af1, As + (mw * 32 + 16) * ASTR + k0, ASTR);
#pragma unroll
            for (int nt = 0; nt < 4; nt++) {
                wmma::fragment<wmma::matrix_b, 16, 16, 16, __half, wmma::row_major> bf;
                wmma::load_matrix_sync(bf, Bs + k0 * BSTR + nw * 64 + nt * 16, BSTR);
                wmma::mma_sync(acc0[nt], af0, bf, acc0[nt]);
                wmma::mma_sync(acc1[nt], af1, bf, acc1[nt]);
            }
        }
    }

    // stage accumulators: per-warp float scratch -> fp16 tile St
    __syncthreads();
    __half* St = (__half*)smraw;                    // 128*136 halves = 34816 B
    float* scratch = (float*)(smraw + 34816);       // 8 warps * 256 floats
    float* myscr = scratch + warp * 256;
#pragma unroll
    for (int mt = 0; mt < 2; mt++) {
#pragma unroll
        for (int nt = 0; nt < 4; nt++) {
            if (mt == 0) {
                wmma::store_matrix_sync(myscr, acc0[nt], 16, wmma::mem_row_major);
            } else {
                wmma::store_matrix_sync(myscr, acc1[nt], 16, wmma::mem_row_major);
            }
            __syncwarp();
#pragma unroll
            for (int q = 0; q < 4; q++) {
                int idx = lane + q * 32;       // 128 half2 slots of a 16x16 tile
                int rr = idx >> 3;
                int cc = (idx & 7) * 2;
                __half2 hv = __floats2half2_rn(myscr[rr * 16 + cc],
                                               myscr[rr * 16 + cc + 1]);
                int gr2 = mw * 32 + mt * 16 + rr;
                int gc = nw * 64 + nt * 16 + cc;
                *(__half2*)(St + gr2 * SSTR + gc) = hv;
            }
            __syncwarp();
        }
    }
    __syncthreads();

    // coalesced fp16 z store
#pragma unroll
    for (int i = 0; i < 8; i++) {
        int lin = tid + i * 256;
        int r = lin >> 4;
        int ch = lin & 15;
        int gr = row0 + r;
        if (gr < NN) {
            float4 v = *(const float4*)(St + r * SSTR + ch * 8);
            *(float4*)(&g_Z1h[rel][(long)gr * 64 + ch * 4]) = v;
        }
    }

    // el/er from staged z: 512 (row,head) pairs, 2 per thread
#pragma unroll
    for (int pp = 0; pp < 2; pp++) {
        int idx = tid + pp * 256;
        int r = idx >> 2;
        int h = idx & 3;
        int gr = row0 + r;
        if (gr < NN) {
            const __half2* zp = (const __half2*)(St + r * SSTR + h * 32);
            const float* alp = alS + h * 32;
            const float* arp = arS + h * 32;
            float el = 0.f;
            float er = 0.f;
#pragma unroll
            for (int f = 0; f < 16; f++) {
                float2 z2 = __half22float2(zp[f]);
                el += z2.x * alp[2 * f] + z2.y * alp[2 * f + 1];
                er += z2.x * arp[2 * f] + z2.y * arp[2 * f + 1];
            }
            g_EL1[rel][gr * 4 + h] = el;
            g_ER1[rel][gr * 4 + h] = er;
        }
    }
}

// ---------------- layer1 fused CSR aggregation (verbatim R4) -----------------
__global__ __launch_bounds__(256) void k_agg1csr(const float* __restrict__ b1) {
    int w = (blockIdx.x * 256 + threadIdx.x) >> 5;
    if (w >= NN) return;
    int d = w;
    int lane = threadIdx.x & 31, h = lane >> 3;
    float acc0 = 0.f, acc1 = 0.f, acc2 = 0.f, acc3 = 0.f;

#pragma unroll
    for (int rel = 0; rel < RR; rel++) {
        float er = g_ER1[rel][d * 4 + h];
        int idx = rel * NN + d;
        int base = g_off[idx], n = g_cnt[idx];
        float a0 = 0.f, a1 = 0.f, a2 = 0.f, a3 = 0.f, den = 0.f;
        int i = 0;
        for (; i + 2 <= n; i += 2) {
            int s0 = g_csrc[base + i];
            int s1 = g_csrc[base + i + 1];
            float el0 = g_EL1[rel][s0 * 4 + h];
            float el1 = g_EL1[rel][s1 * 4 + h];
            h4 z0 = *(const h4*)&g_Z1h[rel][(long)s0 * 64 + lane * 2];
            h4 z1 = *(const h4*)&g_Z1h[rel][(long)s1 * 64 + lane * 2];
            float p0 = lrexp(el0, er);
            float p1 = lrexp(el1, er);
            float2 z0lo = __half22float2(z0.a), z0hi = __half22float2(z0.b);
            float2 z1lo = __half22float2(z1.a), z1hi = __half22float2(z1.b);
            a0 += p0 * z0lo.x + p1 * z1lo.x;
            a1 += p0 * z0lo.y + p1 * z1lo.y;
            a2 += p0 * z0hi.x + p1 * z1hi.x;
            a3 += p0 * z0hi.y + p1 * z1hi.y;
            den += p0 + p1;
        }
        if (i < n) {
            int s = g_csrc[base + i];
            float p = lrexp(g_EL1[rel][s * 4 + h], er);
            h4 z = *(const h4*)&g_Z1h[rel][(long)s * 64 + lane * 2];
            float2 zlo = __half22float2(z.a), zhi = __half22float2(z.b);
            a0 += p * zlo.x; a1 += p * zlo.y; a2 += p * zhi.x; a3 += p * zhi.y;
            den += p;
        }
        float rden = (n > 0) ? __frcp_rn(den) : 0.f;
        acc0 += a0 * rden; acc1 += a1 * rden; acc2 += a2 * rden; acc3 += a3 * rden;
    }
    int c = lane * 4;
    float4 bA = *(const float4*)(b1 + c);
    float4 bB = *(const float4*)(b1 + 128 + c);
    float4 bC = *(const float4*)(b1 + 256 + c);
    float v0 = (acc0 + bA.x + bB.x + bC.x) * (1.f / 3.f);
    float v1 = (acc1 + bA.y + bB.y + bC.y) * (1.f / 3.f);
    float v2 = (acc2 + bA.z + bB.z + bC.z) * (1.f / 3.f);
    float v3 = (acc3 + bA.w + bB.w + bC.w) * (1.f / 3.f);
    v0 = v0 > 0.f ? v0 : expm1f(v0);
    v1 = v1 > 0.f ? v1 : expm1f(v1);
    v2 = v2 > 0.f ? v2 : expm1f(v2);
    v3 = v3 > 0.f ? v3 : expm1f(v3);
    *(float4*)(&g_H1[(long)d * 128 + c]) = make_float4(v0, v1, v2, v3);
}

// ---------------- layer2 GEMM (verbatim R4) ----------------
__global__ __launch_bounds__(256) void k_gemm2(const float* __restrict__ W2,
                                               const float* __restrict__ al2,
                                               const float* __restrict__ ar2) {
    int rel = blockIdx.z;
    int row0 = blockIdx.x * 64;
    __shared__ float xs[64 * 132];
    __shared__ float ws[128 * 16];
    int tid = threadIdx.x;
#pragma unroll
    for (int i = 0; i < 2; i++) {
        int lin = tid + i * 256;
        *(float4*)(ws + lin * 4) = *(const float4*)(W2 + (long)rel * 2048 + lin * 4);
    }
#pragma unroll
    for (int i = 0; i < 8; i++) {
        int lin = tid + i * 256;
        int r = lin >> 5, c4 = lin & 31;
        int grow = row0 + r; if (grow > NN - 1) grow = NN - 1;
        *(float4*)(xs + r * 132 + c4 * 4) =
            *(const float4*)(g_H1 + (long)grow * 128 + c4 * 4);
    }
    __syncthreads();
    int c = tid & 15, rg = tid >> 4;
    float acc[4] = {0.f, 0.f, 0.f, 0.f};
#pragma unroll 8
    for (int k = 0; k < 128; k += 4) {
        float w0 = ws[(k + 0) * 16 + c];
        float w1 = ws[(k + 1) * 16 + c];
        float w2v = ws[(k + 2) * 16 + c];
        float w3 = ws[(k + 3) * 16 + c];
#pragma unroll
        for (int r = 0; r < 4; r++) {
            float4 xv = *(const float4*)(xs + (rg * 4 + r) * 132 + k);
            acc[r] += xv.x * w0 + xv.y * w1 + xv.z * w2v + xv.w * w3;
        }
    }
    float alv = al2[rel * 16 + c], arv = ar2[rel * 16 + c];
#pragma unroll
    for (int r = 0; r < 4; r++) {
        int row = row0 + rg * 4 + r;
        bool ok = row < NN;
        if (ok) g_Z2[rel][(long)row * 16 + c] = acc[r];
        float pe = acc[r] * alv, pr = acc[r] * arv;
#pragma unroll
        for (int off = 8; off >= 1; off >>= 1) {
            pe += __shfl_down_sync(0xffffffffu, pe, off, 16);
            pr += __shfl_down_sync(0xffffffffu, pr, off, 16);
        }
        if (ok && c == 0) { g_EL2[rel][row] = pe; g_ER2[rel][row] = pr; }
    }
}

// ---------------- layer2 fused CSR aggregation (verbatim R4, half->hh) -------
__global__ __launch_bounds__(256) void k_agg2csr(const float* __restrict__ b2,
                                                 float* __restrict__ out) {
    int w = (blockIdx.x * 256 + threadIdx.x) >> 5;
    if (w >= NN) return;
    int d = w;
    int lane = threadIdx.x & 31, hh = lane >> 4, c = lane & 15;
    float acc = 0.f;

#pragma unroll
    for (int rel = 0; rel < RR; rel++) {
        float er = g_ER2[rel][d];
        int idx = rel * NN + d;
        int base = g_off[idx], n = g_cnt[idx];
        float aR = 0.f, den = 0.f;
        for (int i = hh; i < n; i += 2) {
            int s = g_csrc[base + i];
            float p = lrexp(g_EL2[rel][s], er);
            aR += p * g_Z2[rel][s * 16 + c];
            den += p;
        }
        den += __shfl_xor_sync(0xffffffffu, den, 16);
        float rden = (n > 0) ? __frcp_rn(den) : 0.f;
        acc += aR * rden;
    }
    acc += __shfl_xor_sync(0xffffffffu, acc, 16);
    if (hh == 0) {
        float bs = b2[c] + b2[16 + c] + b2[32 + c];
        out[d * 16 + c] = (acc + bs) * (1.f / 3.f);
    }
}

// ---------------- launcher ----------------
extern "C" void kernel_launch(void* const* d_in, const int* in_sizes, int n_in,
                              void* d_out, int out_size) {
    const float* x   = (const float*)d_in[0];
    const int*   src = (const int*)d_in[1];
    const int*   dst = (const int*)d_in[2];
    const float* W1  = (const float*)d_in[3];
    const float* al1 = (const float*)d_in[4];
    const float* ar1 = (const float*)d_in[5];
    const float* b1  = (const float*)d_in[6];
    const float* W2  = (const float*)d_in[7];
    const float* al2 = (const float*)d_in[8];
    const float* ar2 = (const float*)d_in[9];
    const float* b2  = (const float*)d_in[10];
    float* out = (float*)d_out;

    k_zero_cnt<<<(TOT + 255) / 256, 256>>>();
    dim3 ge((EE + 255) / 256, RR);
    k_hist<<<ge, 256>>>(dst);
    k_scan1<<<SCAN_BLK, 256>>>();
    k_scan2<<<1, 512>>>();
    k_scan3<<<SCAN_BLK, 256>>>();
    k_scatter<<<ge, 256>>>(src, dst);

    dim3 gm((NN + 127) / 128, 1, RR);
    k_gemm1_wmma<<<gm, 256>>>(x, W1, al1, ar1);
    k_agg1csr<<<(NN * 32 + 255) / 256, 256>>>(b1);

    dim3 g2((NN + 63) / 64, 1, RR);
    k_gemm2<<<g2, 256>>>(W2, al2, ar2);
    k_agg2csr<<<(NN * 32 + 255) / 256, 256>>>(b2, out);
}

// round 9
// speedup vs baseline: 2.3097x; 1.0538x over previous
#include <cuda_runtime.h>
#include <cuda_fp16.h>
#include <mma.h>
#include <math.h>

using namespace nvcuda;

#define NN 100000
#define RR 3
#define EE 1600000
#define TOT (RR * NN)
#define SCAN_BLK 293

__device__ __align__(16) __half2 g_Z1h[RR][(long)NN * 64];
__device__ __align__(16) float g_EL1[RR][NN * 4];
__device__ __align__(16) float g_ER1[RR][NN * 4];
__device__ __align__(16) float g_H1[(long)NN * 128];
__device__ __align__(16) float g_Z2[RR][NN * 16];
__device__ __align__(16) float g_EL2[RR][NN];
__device__ __align__(16) float g_ER2[RR][NN];

__device__ int g_cnt[TOT];
__device__ int g_off[TOT];
__device__ int g_cur[TOT];
__device__ int g_bsum[SCAN_BLK + 1];
__device__ int g_csrc[RR * EE];

struct __align__(8) h4 { __half2 a, b; };

__device__ __forceinline__ float lrexp(float a, float b) {
    float e = a + b;
    e = e > 0.f ? e : 0.2f * e;
    return __expf(e);
}

// ---------------- CSR build ----------------
__global__ void k_zero_cnt() {
    int i = blockIdx.x * 256 + threadIdx.x;
    if (i < TOT) g_cnt[i] = 0;
}

__global__ __launch_bounds__(256) void k_hist(const int* __restrict__ dst) {
    int rel = blockIdx.y;
    long e = blockIdx.x * 256L + threadIdx.x;
    if (e >= EE) return;
    int d = dst[(long)rel * EE + e];
    atomicAdd(&g_cnt[rel * NN + d], 1);
}

__global__ __launch_bounds__(256) void k_scan1() {
    __shared__ int sm[256];
    int t = threadIdx.x;
    int base = blockIdx.x * 1024 + t * 4;
    int v[4];
#pragma unroll
    for (int k = 0; k < 4; k++) v[k] = (base + k < TOT) ? g_cnt[base + k] : 0;
    int tsum = v[0] + v[1] + v[2] + v[3];
    sm[t] = tsum;
    __syncthreads();
    for (int off = 1; off < 256; off <<= 1) {
        int x = (t >= off) ? sm[t - off] : 0;
        __syncthreads();
        sm[t] += x;
        __syncthreads();
    }
    int run = sm[t] - tsum;
#pragma unroll
    for (int k = 0; k < 4; k++) {
        if (base + k < TOT) g_off[base + k] = run;
        run += v[k];
    }
    if (t == 255) g_bsum[blockIdx.x] = sm[255];
}

__global__ void k_scan2() {
    __shared__ int sm[512];
    int t = threadIdx.x;
    sm[t] = (t < SCAN_BLK) ? g_bsum[t] : 0;
    __syncthreads();
    for (int off = 1; off < 512; off <<= 1) {
        int x = (t >= off) ? sm[t - off] : 0;
        __syncthreads();
        sm[t] += x;
        __syncthreads();
    }
    if (t < SCAN_BLK) g_bsum[t] = (t == 0) ? 0 : sm[t - 1];
}

__global__ __launch_bounds__(256) void k_scan3() {
    int t = threadIdx.x;
    int base = blockIdx.x * 1024 + t * 4;
    int add = g_bsum[blockIdx.x];
#pragma unroll
    for (int k = 0; k < 4; k++) {
        if (base + k < TOT) {
            int o = g_off[base + k] + add;
            g_off[base + k] = o;
            g_cur[base + k] = o;
        }
    }
}

__global__ __launch_bounds__(256) void k_scatter(const int* __restrict__ src,
                                                 const int* __restrict__ dst) {
    int rel = blockIdx.y;
    long e = blockIdx.x * 256L + threadIdx.x;
    if (e >= EE) return;
    int s = src[(long)rel * EE + e];
    int d = dst[(long)rel * EE + e];
    int pos = atomicAdd(&g_cur[rel * NN + d], 1);
    g_csrc[pos] = s;
}

// ---------------- layer1 GEMM on tensor cores via wmma -----------------------
#define ASTR 72
#define BSTR 136
#define SSTR 136
__global__ __launch_bounds__(256) void k_gemm1_wmma(const float* __restrict__ x,
                                                    const float* __restrict__ W1,
                                                    const float* __restrict__ al1,
                                                    const float* __restrict__ ar1) {
    __shared__ __align__(16) char smraw[43008];
    __shared__ float alS[128];
    __shared__ float arS[128];
    __half* As = (__half*)smraw;                  // 128*72 halves = 18432 B
    __half* Bs = (__half*)(smraw + 18432);        // 64*136 halves = 17408 B
    int rel = blockIdx.z;
    int row0 = blockIdx.x * 128;
    int tid = threadIdx.x;
    int lane = tid & 31;
    int warp = tid >> 5;
    int mw = warp & 3;
    int nw = warp >> 2;
    const float* Wp = W1 + (long)rel * 16384;

    if (tid < 128) {
        alS[tid] = al1[rel * 128 + tid];
        arS[tid] = ar1[rel * 128 + tid];
    }

    wmma::fragment<wmma::accumulator, 16, 16, 16, float> acc0[4];
    wmma::fragment<wmma::accumulator, 16, 16, 16, float> acc1[4];
#pragma unroll
    for (int nt = 0; nt < 4; nt++) {
        wmma::fill_fragment(acc0[nt], 0.f);
        wmma::fill_fragment(acc1[nt], 0.f);
    }

    for (int kh = 0; kh < 2; kh++) {
        if (kh) __syncthreads();
#pragma unroll
        for (int i = 0; i < 8; i++) {
            int lin = tid + i * 256;
            int r = lin >> 4;
            int c4 = lin & 15;
            int gr = row0 + r;
            if (gr >= NN) gr = NN - 1;
            float4 v = *(const float4*)(x + (long)gr * 128 + kh * 64 + c4 * 4);
            __half2* p = (__half2*)(As + r * ASTR + c4 * 4);
            p[0] = __floats2half2_rn(v.x, v.y);
            p[1] = __floats2half2_rn(v.z, v.w);
        }
#pragma unroll
        for (int i = 0; i < 8; i++) {
            int lin = tid + i * 256;
            int r = lin >> 5;
            int c4 = lin & 31;
            float4 v = *(const float4*)(Wp + (long)(kh * 64 + r) * 128 + c4 * 4);
            __half2* p = (__half2*)(Bs + r * BSTR + c4 * 4);
            p[0] = __floats2half2_rn(v.x, v.y);
            p[1] = __floats2half2_rn(v.z, v.w);
        }
        __syncthreads();
#pragma unroll
        for (int ks = 0; ks < 4; ks++) {
            int k0 = ks * 16;
            wmma::fragment<wmma::matrix_a, 16, 16, 16, __half, wmma::row_major> af0;
            wmma::fragment<wmma::matrix_a, 16, 16, 16, __half, wmma::row_major> af1;
            wmma::load_matrix_sync(af0, As + (mw * 32) * ASTR + k0, ASTR);
            wmma::load_matrix_sync(af1, As + (mw * 32 + 16) * ASTR + k0, ASTR);
#pragma unroll
            for (int nt = 0; nt < 4; nt++) {
                wmma::fragment<wmma::matrix_b, 16, 16, 16, __half, wmma::row_major> bf;
                wmma::load_matrix_sync(bf, Bs + k0 * BSTR + nw * 64 + nt * 16, BSTR);
                wmma::mma_sync(acc0[nt], af0, bf, acc0[nt]);
                wmma::mma_sync(acc1[nt], af1, bf, acc1[nt]);
            }
        }
    }

    __syncthreads();
    __half* St = (__half*)smraw;                    // 128*136 halves = 34816 B
    float* scratch = (float*)(smraw + 34816);       // 8 warps * 256 floats
    float* myscr = scratch + warp * 256;
#pragma unroll
    for (int mt = 0; mt < 2; mt++) {
#pragma unroll
        for (int nt = 0; nt < 4; nt++) {
            if (mt == 0) {
                wmma::store_matrix_sync(myscr, acc0[nt], 16, wmma::mem_row_major);
            } else {
                wmma::store_matrix_sync(myscr, acc1[nt], 16, wmma::mem_row_major);
            }
            __syncwarp();
#pragma unroll
            for (int q = 0; q < 4; q++) {
                int idx = lane + q * 32;
                int rr = idx >> 3;
                int cc = (idx & 7) * 2;
                __half2 hv = __floats2half2_rn(myscr[rr * 16 + cc],
                                               myscr[rr * 16 + cc + 1]);
                int gr2 = mw * 32 + mt * 16 + rr;
                int gc = nw * 64 + nt * 16 + cc;
                *(__half2*)(St + gr2 * SSTR + gc) = hv;
            }
            __syncwarp();
        }
    }
    __syncthreads();

#pragma unroll
    for (int i = 0; i < 8; i++) {
        int lin = tid + i * 256;
        int r = lin >> 4;
        int ch = lin & 15;
        int gr = row0 + r;
        if (gr < NN) {
            float4 v = *(const float4*)(St + r * SSTR + ch * 8);
            *(float4*)(&g_Z1h[rel][(long)gr * 64 + ch * 4]) = v;
        }
    }

#pragma unroll
    for (int pp = 0; pp < 2; pp++) {
        int idx = tid + pp * 256;
        int r = idx >> 2;
        int h = idx & 3;
        int gr = row0 + r;
        if (gr < NN) {
            const __half2* zp = (const __half2*)(St + r * SSTR + h * 32);
            const float* alp = alS + h * 32;
            const float* arp = arS + h * 32;
            float el = 0.f;
            float er = 0.f;
#pragma unroll
            for (int f = 0; f < 16; f++) {
                float2 z2 = __half22float2(zp[f]);
                el += z2.x * alp[2 * f] + z2.y * alp[2 * f + 1];
                er += z2.x * arp[2 * f] + z2.y * arp[2 * f + 1];
            }
            g_EL1[rel][gr * 4 + h] = el;
            g_ER1[rel][gr * 4 + h] = er;
        }
    }
}

// ---------------- layer1 fused CSR aggregation (4-way unrolled) --------------
__global__ __launch_bounds__(256) void k_agg1csr(const float* __restrict__ b1) {
    int w = (blockIdx.x * 256 + threadIdx.x) >> 5;
    if (w >= NN) return;
    int d = w;
    int lane = threadIdx.x & 31, h = lane >> 3;
    float acc0 = 0.f, acc1 = 0.f, acc2 = 0.f, acc3 = 0.f;

#pragma unroll
    for (int rel = 0; rel < RR; rel++) {
        float er = g_ER1[rel][d * 4 + h];
        int idx = rel * NN + d;
        int base = g_off[idx], n = g_cnt[idx];
        float a0 = 0.f, a1 = 0.f, a2 = 0.f, a3 = 0.f, den = 0.f;
        int i = 0;
        for (; i + 4 <= n; i += 4) {
            int s0 = g_csrc[base + i];
            int s1 = g_csrc[base + i + 1];
            int s2 = g_csrc[base + i + 2];
            int s3 = g_csrc[base + i + 3];
            float el0 = g_EL1[rel][s0 * 4 + h];
            float el1 = g_EL1[rel][s1 * 4 + h];
            float el2 = g_EL1[rel][s2 * 4 + h];
            float el3 = g_EL1[rel][s3 * 4 + h];
            h4 z0 = *(const h4*)&g_Z1h[rel][(long)s0 * 64 + lane * 2];
            h4 z1 = *(const h4*)&g_Z1h[rel][(long)s1 * 64 + lane * 2];
            h4 z2 = *(const h4*)&g_Z1h[rel][(long)s2 * 64 + lane * 2];
            h4 z3 = *(const h4*)&g_Z1h[rel][(long)s3 * 64 + lane * 2];
            float p0 = lrexp(el0, er);
            float p1 = lrexp(el1, er);
            float p2 = lrexp(el2, er);
            float p3 = lrexp(el3, er);
            float2 q0 = __half22float2(z0.a), r0 = __half22float2(z0.b);
            float2 q1 = __half22float2(z1.a), r1 = __half22float2(z1.b);
            float2 q2 = __half22float2(z2.a), r2 = __half22float2(z2.b);
            float2 q3 = __half22float2(z3.a), r3 = __half22float2(z3.b);
            a0 += p0 * q0.x + p1 * q1.x + p2 * q2.x + p3 * q3.x;
            a1 += p0 * q0.y + p1 * q1.y + p2 * q2.y + p3 * q3.y;
            a2 += p0 * r0.x + p1 * r1.x + p2 * r2.x + p3 * r3.x;
            a3 += p0 * r0.y + p1 * r1.y + p2 * r2.y + p3 * r3.y;
            den += p0 + p1 + p2 + p3;
        }
        for (; i < n; i++) {
            int s = g_csrc[base + i];
            float p = lrexp(g_EL1[rel][s * 4 + h], er);
            h4 z = *(const h4*)&g_Z1h[rel][(long)s * 64 + lane * 2];
            float2 zlo = __half22float2(z.a), zhi = __half22float2(z.b);
            a0 += p * zlo.x; a1 += p * zlo.y; a2 += p * zhi.x; a3 += p * zhi.y;
            den += p;
        }
        float rden = (n > 0) ? __frcp_rn(den) : 0.f;
        acc0 += a0 * rden; acc1 += a1 * rden; acc2 += a2 * rden; acc3 += a3 * rden;
    }
    int c = lane * 4;
    float4 bA = *(const float4*)(b1 + c);
    float4 bB = *(const float4*)(b1 + 128 + c);
    float4 bC = *(const float4*)(b1 + 256 + c);
    float v0 = (acc0 + bA.x + bB.x + bC.x) * (1.f / 3.f);
    float v1 = (acc1 + bA.y + bB.y + bC.y) * (1.f / 3.f);
    float v2 = (acc2 + bA.z + bB.z + bC.z) * (1.f / 3.f);
    float v3 = (acc3 + bA.w + bB.w + bC.w) * (1.f / 3.f);
    v0 = v0 > 0.f ? v0 : expm1f(v0);
    v1 = v1 > 0.f ? v1 : expm1f(v1);
    v2 = v2 > 0.f ? v2 : expm1f(v2);
    v3 = v3 > 0.f ? v3 : expm1f(v3);
    *(float4*)(&g_H1[(long)d * 128 + c]) = make_float4(v0, v1, v2, v3);
}

// ---------------- layer2 GEMM (fp32 SIMT) ----------------
__global__ __launch_bounds__(256) void k_gemm2(const float* __restrict__ W2,
                                               const float* __restrict__ al2,
                                               const float* __restrict__ ar2) {
    int rel = blockIdx.z;
    int row0 = blockIdx.x * 64;
    __shared__ float xs[64 * 132];
    __shared__ float ws[128 * 16];
    int tid = threadIdx.x;
#pragma unroll
    for (int i = 0; i < 2; i++) {
        int lin = tid + i * 256;
        *(float4*)(ws + lin * 4) = *(const float4*)(W2 + (long)rel * 2048 + lin * 4);
    }
#pragma unroll
    for (int i = 0; i < 8; i++) {
        int lin = tid + i * 256;
        int r = lin >> 5, c4 = lin & 31;
        int grow = row0 + r; if (grow > NN - 1) grow = NN - 1;
        *(float4*)(xs + r * 132 + c4 * 4) =
            *(const float4*)(g_H1 + (long)grow * 128 + c4 * 4);
    }
    __syncthreads();
    int c = tid & 15, rg = tid >> 4;
    float acc[4] = {0.f, 0.f, 0.f, 0.f};
#pragma unroll 8
    for (int k = 0; k < 128; k += 4) {
        float w0 = ws[(k + 0) * 16 + c];
        float w1 = ws[(k + 1) * 16 + c];
        float w2v = ws[(k + 2) * 16 + c];
        float w3 = ws[(k + 3) * 16 + c];
#pragma unroll
        for (int r = 0; r < 4; r++) {
            float4 xv = *(const float4*)(xs + (rg * 4 + r) * 132 + k);
            acc[r] += xv.x * w0 + xv.y * w1 + xv.z * w2v + xv.w * w3;
        }
    }
    float alv = al2[rel * 16 + c], arv = ar2[rel * 16 + c];
#pragma unroll
    for (int r = 0; r < 4; r++) {
        int row = row0 + rg * 4 + r;
        bool ok = row < NN;
        if (ok) g_Z2[rel][(long)row * 16 + c] = acc[r];
        float pe = acc[r] * alv, pr = acc[r] * arv;
#pragma unroll
        for (int off = 8; off >= 1; off >>= 1) {
            pe += __shfl_down_sync(0xffffffffu, pe, off, 16);
            pr += __shfl_down_sync(0xffffffffu, pr, off, 16);
        }
        if (ok && c == 0) { g_EL2[rel][row] = pe; g_ER2[rel][row] = pr; }
    }
}

// ---------------- layer2 fused CSR aggregation (2-way per half-warp) ---------
__global__ __launch_bounds__(256) void k_agg2csr(const float* __restrict__ b2,
                                                 float* __restrict__ out) {
    int w = (blockIdx.x * 256 + threadIdx.x) >> 5;
    if (w >= NN) return;
    int d = w;
    int lane = threadIdx.x & 31, hh = lane >> 4, c = lane & 15;
    float acc = 0.f;

#pragma unroll
    for (int rel = 0; rel < RR; rel++) {
        float er = g_ER2[rel][d];
        int idx = rel * NN + d;
        int base = g_off[idx], n = g_cnt[idx];
        float aR = 0.f, den = 0.f;
        int i = hh;
        for (; i + 2 < n; i += 4) {
            int s0 = g_csrc[base + i];
            int s1 = g_csrc[base + i + 2];
            float e0 = g_EL2[rel][s0];
            float e1 = g_EL2[rel][s1];
            float za = g_Z2[rel][s0 * 16 + c];
            float zb = g_Z2[rel][s1 * 16 + c];
            float p0 = lrexp(e0, er);
            float p1 = lrexp(e1, er);
            aR += p0 * za + p1 * zb;
            den += p0 + p1;
        }
        if (i < n) {
            int s = g_csrc[base + i];
            float p = lrexp(g_EL2[rel][s], er);
            aR += p * g_Z2[rel][s * 16 + c];
            den += p;
        }
        den += __shfl_xor_sync(0xffffffffu, den, 16);
        float rden = (n > 0) ? __frcp_rn(den) : 0.f;
        acc += aR * rden;
    }
    acc += __shfl_xor_sync(0xffffffffu, acc, 16);
    if (hh == 0) {
        float bs = b2[c] + b2[16 + c] + b2[32 + c];
        out[d * 16 + c] = (acc + bs) * (1.f / 3.f);
    }
}

// ---------------- launcher (gemm1 moved to launch index 3 for profiling) -----
extern "C" void kernel_launch(void* const* d_in, const int* in_sizes, int n_in,
                              void* d_out, int out_size) {
    const float* x   = (const float*)d_in[0];
    const int*   src = (const int*)d_in[1];
    const int*   dst = (const int*)d_in[2];
    const float* W1  = (const float*)d_in[3];
    const float* al1 = (const float*)d_in[4];
    const float* ar1 = (const float*)d_in[5];
    const float* b1  = (const float*)d_in[6];
    const float* W2  = (const float*)d_in[7];
    const float* al2 = (const float*)d_in[8];
    const float* ar2 = (const float*)d_in[9];
    const float* b2  = (const float*)d_in[10];
    float* out = (float*)d_out;

    k_zero_cnt<<<(TOT + 255) / 256, 256>>>();
    dim3 ge((EE + 255) / 256, RR);
    k_hist<<<ge, 256>>>(dst);
    k_scan1<<<SCAN_BLK, 256>>>();

    dim3 gm((NN + 127) / 128, 1, RR);
    k_gemm1_wmma<<<gm, 256>>>(x, W1, al1, ar1);   // launch index 3 (profiled)

    k_scan2<<<1, 512>>>();
    k_scan3<<<SCAN_BLK, 256>>>();
    k_scatter<<<ge, 256>>>(src, dst);

    k_agg1csr<<<(NN * 32 + 255) / 256, 256>>>(b1);

    dim3 g2((NN + 63) / 64, 1, RR);
    k_gemm2<<<g2, 256>>>(W2, al2, ar2);
    k_agg2csr<<<(NN * 32 + 255) / 256, 256>>>(b2, out);
}

// round 10
// speedup vs baseline: 2.4667x; 1.0680x over previous
#include <cuda_runtime.h>
#include <cuda_fp16.h>
#include <mma.h>
#include <math.h>

using namespace nvcuda;

#define NN 100000
#define RR 3
#define EE 1600000
#define TOT (RR * NN)
#define SCAN_BLK 293

__device__ __align__(16) __half2 g_Z1h[RR][(long)NN * 64];
__device__ __align__(16) float g_EL1[RR][NN * 4];
__device__ __align__(16) float g_ER1[RR][NN * 4];
__device__ __align__(16) __half2 g_H1h[(long)NN * 64];
__device__ __align__(16) float g_Z2[RR][NN * 16];
__device__ __align__(16) float g_EL2[RR][NN];
__device__ __align__(16) float g_ER2[RR][NN];

__device__ int g_cnt[TOT];
__device__ int g_off[TOT];
__device__ int g_cur[TOT];
__device__ int g_bsum[SCAN_BLK + 1];
__device__ int g_csrc[RR * EE];

struct __align__(8) h4 { __half2 a, b; };

__device__ __forceinline__ float lrexp(float a, float b) {
    float e = a + b;
    e = e > 0.f ? e : 0.2f * e;
    return __expf(e);
}

// ---------------- CSR build ----------------
__global__ void k_zero_cnt() {
    int i = blockIdx.x * 256 + threadIdx.x;
    if (i < TOT) g_cnt[i] = 0;
}

__global__ __launch_bounds__(256) void k_hist(const int* __restrict__ dst) {
    int rel = blockIdx.y;
    long e = blockIdx.x * 256L + threadIdx.x;
    if (e >= EE) return;
    int d = dst[(long)rel * EE + e];
    atomicAdd(&g_cnt[rel * NN + d], 1);
}

__global__ __launch_bounds__(256) void k_scan1() {
    __shared__ int sm[256];
    int t = threadIdx.x;
    int base = blockIdx.x * 1024 + t * 4;
    int v[4];
#pragma unroll
    for (int k = 0; k < 4; k++) v[k] = (base + k < TOT) ? g_cnt[base + k] : 0;
    int tsum = v[0] + v[1] + v[2] + v[3];
    sm[t] = tsum;
    __syncthreads();
    for (int off = 1; off < 256; off <<= 1) {
        int x = (t >= off) ? sm[t - off] : 0;
        __syncthreads();
        sm[t] += x;
        __syncthreads();
    }
    int run = sm[t] - tsum;
#pragma unroll
    for (int k = 0; k < 4; k++) {
        if (base + k < TOT) g_off[base + k] = run;
        run += v[k];
    }
    if (t == 255) g_bsum[blockIdx.x] = sm[255];
}

__global__ void k_scan2() {
    __shared__ int sm[512];
    int t = threadIdx.x;
    sm[t] = (t < SCAN_BLK) ? g_bsum[t] : 0;
    __syncthreads();
    for (int off = 1; off < 512; off <<= 1) {
        int x = (t >= off) ? sm[t - off] : 0;
        __syncthreads();
        sm[t] += x;
        __syncthreads();
    }
    if (t < SCAN_BLK) g_bsum[t] = (t == 0) ? 0 : sm[t - 1];
}

__global__ __launch_bounds__(256) void k_scan3() {
    int t = threadIdx.x;
    int base = blockIdx.x * 1024 + t * 4;
    int add = g_bsum[blockIdx.x];
#pragma unroll
    for (int k = 0; k < 4; k++) {
        if (base + k < TOT) {
            int o = g_off[base + k] + add;
            g_off[base + k] = o;
            g_cur[base + k] = o;
        }
    }
}

__global__ __launch_bounds__(256) void k_scatter(const int* __restrict__ src,
                                                 const int* __restrict__ dst) {
    int rel = blockIdx.y;
    long e = blockIdx.x * 256L + threadIdx.x;
    if (e >= EE) return;
    int s = src[(long)rel * EE + e];
    int d = dst[(long)rel * EE + e];
    int pos = atomicAdd(&g_cur[rel * NN + d], 1);
    g_csrc[pos] = s;
}

// ---------------- layer1 GEMM (wmma, unchanged from R9) ----------------------
#define ASTR 72
#define BSTR 136
#define SSTR 136
__global__ __launch_bounds__(256) void k_gemm1_wmma(const float* __restrict__ x,
                                                    const float* __restrict__ W1,
                                                    const float* __restrict__ al1,
                                                    const float* __restrict__ ar1) {
    __shared__ __align__(16) char smraw[43008];
    __shared__ float alS[128];
    __shared__ float arS[128];
    __half* As = (__half*)smraw;
    __half* Bs = (__half*)(smraw + 18432);
    int rel = blockIdx.z;
    int row0 = blockIdx.x * 128;
    int tid = threadIdx.x;
    int lane = tid & 31;
    int warp = tid >> 5;
    int mw = warp & 3;
    int nw = warp >> 2;
    const float* Wp = W1 + (long)rel * 16384;

    if (tid < 128) {
        alS[tid] = al1[rel * 128 + tid];
        arS[tid] = ar1[rel * 128 + tid];
    }

    wmma::fragment<wmma::accumulator, 16, 16, 16, float> acc0[4];
    wmma::fragment<wmma::accumulator, 16, 16, 16, float> acc1[4];
#pragma unroll
    for (int nt = 0; nt < 4; nt++) {
        wmma::fill_fragment(acc0[nt], 0.f);
        wmma::fill_fragment(acc1[nt], 0.f);
    }

    for (int kh = 0; kh < 2; kh++) {
        if (kh) __syncthreads();
#pragma unroll
        for (int i = 0; i < 8; i++) {
            int lin = tid + i * 256;
            int r = lin >> 4;
            int c4 = lin & 15;
            int gr = row0 + r;
            if (gr >= NN) gr = NN - 1;
            float4 v = *(const float4*)(x + (long)gr * 128 + kh * 64 + c4 * 4);
            __half2* p = (__half2*)(As + r * ASTR + c4 * 4);
            p[0] = __floats2half2_rn(v.x, v.y);
            p[1] = __floats2half2_rn(v.z, v.w);
        }
#pragma unroll
        for (int i = 0; i < 8; i++) {
            int lin = tid + i * 256;
            int r = lin >> 5;
            int c4 = lin & 31;
            float4 v = *(const float4*)(Wp + (long)(kh * 64 + r) * 128 + c4 * 4);
            __half2* p = (__half2*)(Bs + r * BSTR + c4 * 4);
            p[0] = __floats2half2_rn(v.x, v.y);
            p[1] = __floats2half2_rn(v.z, v.w);
        }
        __syncthreads();
#pragma unroll
        for (int ks = 0; ks < 4; ks++) {
            int k0 = ks * 16;
            wmma::fragment<wmma::matrix_a, 16, 16, 16, __half, wmma::row_major> af0;
            wmma::fragment<wmma::matrix_a, 16, 16, 16, __half, wmma::row_major> af1;
            wmma::load_matrix_sync(af0, As + (mw * 32) * ASTR + k0, ASTR);
            wmma::load_matrix_sync(af1, As + (mw * 32 + 16) * ASTR + k0, ASTR);
#pragma unroll
            for (int nt = 0; nt < 4; nt++) {
                wmma::fragment<wmma::matrix_b, 16, 16, 16, __half, wmma::row_major> bf;
                wmma::load_matrix_sync(bf, Bs + k0 * BSTR + nw * 64 + nt * 16, BSTR);
                wmma::mma_sync(acc0[nt], af0, bf, acc0[nt]);
                wmma::mma_sync(acc1[nt], af1, bf, acc1[nt]);
            }
        }
    }

    __syncthreads();
    __half* St = (__half*)smraw;
    float* scratch = (float*)(smraw + 34816);
    float* myscr = scratch + warp * 256;
#pragma unroll
    for (int mt = 0; mt < 2; mt++) {
#pragma unroll
        for (int nt = 0; nt < 4; nt++) {
            if (mt == 0) {
                wmma::store_matrix_sync(myscr, acc0[nt], 16, wmma::mem_row_major);
            } else {
                wmma::store_matrix_sync(myscr, acc1[nt], 16, wmma::mem_row_major);
            }
            __syncwarp();
#pragma unroll
            for (int q = 0; q < 4; q++) {
                int idx = lane + q * 32;
                int rr = idx >> 3;
                int cc = (idx & 7) * 2;
                __half2 hv = __floats2half2_rn(myscr[rr * 16 + cc],
                                               myscr[rr * 16 + cc + 1]);
                int gr2 = mw * 32 + mt * 16 + rr;
                int gc = nw * 64 + nt * 16 + cc;
                *(__half2*)(St + gr2 * SSTR + gc) = hv;
            }
            __syncwarp();
        }
    }
    __syncthreads();

#pragma unroll
    for (int i = 0; i < 8; i++) {
        int lin = tid + i * 256;
        int r = lin >> 4;
        int ch = lin & 15;
        int gr = row0 + r;
        if (gr < NN) {
            float4 v = *(const float4*)(St + r * SSTR + ch * 8);
            *(float4*)(&g_Z1h[rel][(long)gr * 64 + ch * 4]) = v;
        }
    }

#pragma unroll
    for (int pp = 0; pp < 2; pp++) {
        int idx = tid + pp * 256;
        int r = idx >> 2;
        int h = idx & 3;
        int gr = row0 + r;
        if (gr < NN) {
            const __half2* zp = (const __half2*)(St + r * SSTR + h * 32);
            const float* alp = alS + h * 32;
            const float* arp = arS + h * 32;
            float el = 0.f;
            float er = 0.f;
#pragma unroll
            for (int f = 0; f < 16; f++) {
                float2 z2 = __half22float2(zp[f]);
                el += z2.x * alp[2 * f] + z2.y * alp[2 * f + 1];
                er += z2.x * arp[2 * f] + z2.y * arp[2 * f + 1];
            }
            g_EL1[rel][gr * 4 + h] = el;
            g_ER1[rel][gr * 4 + h] = er;
        }
    }
}

// ------- layer1 fused CSR aggregation: hoisted metadata, 8-way, fp16 out -----
__global__ __launch_bounds__(256) void k_agg1csr(const float* __restrict__ b1) {
    int w = (blockIdx.x * 256 + threadIdx.x) >> 5;
    if (w >= NN) return;
    int d = w;
    int lane = threadIdx.x & 31, h = lane >> 3;
    float acc0 = 0.f, acc1 = 0.f, acc2 = 0.f, acc3 = 0.f;

    int baseA[RR];
    int cntA[RR];
    float erv[RR];
#pragma unroll
    for (int rel = 0; rel < RR; rel++) {
        int idx = rel * NN + d;
        baseA[rel] = g_off[idx];
        cntA[rel] = g_cnt[idx];
        erv[rel] = g_ER1[rel][d * 4 + h];
    }

#pragma unroll
    for (int rel = 0; rel < RR; rel++) {
        float er = erv[rel];
        int base = baseA[rel], n = cntA[rel];
        float a0 = 0.f, a1 = 0.f, a2 = 0.f, a3 = 0.f, den = 0.f;
        int i = 0;
        for (; i + 8 <= n; i += 8) {
            int s0 = g_csrc[base + i];
            int s1 = g_csrc[base + i + 1];
            int s2 = g_csrc[base + i + 2];
            int s3 = g_csrc[base + i + 3];
            int s4 = g_csrc[base + i + 4];
            int s5 = g_csrc[base + i + 5];
            int s6 = g_csrc[base + i + 6];
            int s7 = g_csrc[base + i + 7];
            float el0 = g_EL1[rel][s0 * 4 + h];
            float el1 = g_EL1[rel][s1 * 4 + h];
            float el2 = g_EL1[rel][s2 * 4 + h];
            float el3 = g_EL1[rel][s3 * 4 + h];
            float el4 = g_EL1[rel][s4 * 4 + h];
            float el5 = g_EL1[rel][s5 * 4 + h];
            float el6 = g_EL1[rel][s6 * 4 + h];
            float el7 = g_EL1[rel][s7 * 4 + h];
            h4 z0 = *(const h4*)&g_Z1h[rel][(long)s0 * 64 + lane * 2];
            h4 z1 = *(const h4*)&g_Z1h[rel][(long)s1 * 64 + lane * 2];
            h4 z2 = *(const h4*)&g_Z1h[rel][(long)s2 * 64 + lane * 2];
            h4 z3 = *(const h4*)&g_Z1h[rel][(long)s3 * 64 + lane * 2];
            h4 z4 = *(const h4*)&g_Z1h[rel][(long)s4 * 64 + lane * 2];
            h4 z5 = *(const h4*)&g_Z1h[rel][(long)s5 * 64 + lane * 2];
            h4 z6 = *(const h4*)&g_Z1h[rel][(long)s6 * 64 + lane * 2];
            h4 z7 = *(const h4*)&g_Z1h[rel][(long)s7 * 64 + lane * 2];
            float p0 = lrexp(el0, er);
            float p1 = lrexp(el1, er);
            float p2 = lrexp(el2, er);
            float p3 = lrexp(el3, er);
            float p4 = lrexp(el4, er);
            float p5 = lrexp(el5, er);
            float p6 = lrexp(el6, er);
            float p7 = lrexp(el7, er);
            float2 q0 = __half22float2(z0.a), r0 = __half22float2(z0.b);
            float2 q1 = __half22float2(z1.a), r1 = __half22float2(z1.b);
            float2 q2 = __half22float2(z2.a), r2 = __half22float2(z2.b);
            float2 q3 = __half22float2(z3.a), r3 = __half22float2(z3.b);
            float2 q4 = __half22float2(z4.a), r4 = __half22float2(z4.b);
            float2 q5 = __half22float2(z5.a), r5 = __half22float2(z5.b);
            float2 q6 = __half22float2(z6.a), r6 = __half22float2(z6.b);
            float2 q7 = __half22float2(z7.a), r7 = __half22float2(z7.b);
            a0 += p0 * q0.x + p1 * q1.x + p2 * q2.x + p3 * q3.x
                + p4 * q4.x + p5 * q5.x + p6 * q6.x + p7 * q7.x;
            a1 += p0 * q0.y + p1 * q1.y + p2 * q2.y + p3 * q3.y
                + p4 * q4.y + p5 * q5.y + p6 * q6.y + p7 * q7.y;
            a2 += p0 * r0.x + p1 * r1.x + p2 * r2.x + p3 * r3.x
                + p4 * r4.x + p5 * r5.x + p6 * r6.x + p7 * r7.x;
            a3 += p0 * r0.y + p1 * r1.y + p2 * r2.y + p3 * r3.y
                + p4 * r4.y + p5 * r5.y + p6 * r6.y + p7 * r7.y;
            den += p0 + p1 + p2 + p3 + p4 + p5 + p6 + p7;
        }
        for (; i < n; i++) {
            int s = g_csrc[base + i];
            float p = lrexp(g_EL1[rel][s * 4 + h], er);
            h4 z = *(const h4*)&g_Z1h[rel][(long)s * 64 + lane * 2];
            float2 zlo = __half22float2(z.a), zhi = __half22float2(z.b);
            a0 += p * zlo.x; a1 += p * zlo.y; a2 += p * zhi.x; a3 += p * zhi.y;
            den += p;
        }
        float rden = (n > 0) ? __frcp_rn(den) : 0.f;
        acc0 += a0 * rden; acc1 += a1 * rden; acc2 += a2 * rden; acc3 += a3 * rden;
    }
    int c = lane * 4;
    float4 bA = *(const float4*)(b1 + c);
    float4 bB = *(const float4*)(b1 + 128 + c);
    float4 bC = *(const float4*)(b1 + 256 + c);
    float v0 = (acc0 + bA.x + bB.x + bC.x) * (1.f / 3.f);
    float v1 = (acc1 + bA.y + bB.y + bC.y) * (1.f / 3.f);
    float v2 = (acc2 + bA.z + bB.z + bC.z) * (1.f / 3.f);
    float v3 = (acc3 + bA.w + bB.w + bC.w) * (1.f / 3.f);
    v0 = v0 > 0.f ? v0 : expm1f(v0);
    v1 = v1 > 0.f ? v1 : expm1f(v1);
    v2 = v2 > 0.f ? v2 : expm1f(v2);
    v3 = v3 > 0.f ? v3 : expm1f(v3);
    h4 hv;
    hv.a = __floats2half2_rn(v0, v1);
    hv.b = __floats2half2_rn(v2, v3);
    *(h4*)(&g_H1h[(long)d * 64 + lane * 2]) = hv;
}

// ---------------- layer2 GEMM via wmma (fp16 H1h input) ----------------------
#define A2STR 136
#define B2STR 24
__global__ __launch_bounds__(256) void k_gemm2_wmma(const float* __restrict__ W2,
                                                    const float* __restrict__ al2,
                                                    const float* __restrict__ ar2) {
    __shared__ __align__(16) char smraw2[40960];   // As2 34816 + Bs2 6144
    __shared__ float al2S[16];
    __shared__ float ar2S[16];
    __half* As2 = (__half*)smraw2;
    __half* Bs2 = (__half*)(smraw2 + 34816);
    int rel = blockIdx.z;
    int row0 = blockIdx.x * 128;
    int tid = threadIdx.x;
    int lane = tid & 31;
    int warp = tid >> 5;

    if (tid < 16) {
        al2S[tid] = al2[rel * 16 + tid];
        ar2S[tid] = ar2[rel * 16 + tid];
    }

    // As2: 128 rows x 128 cols fp16 from g_H1h
#pragma unroll
    for (int i = 0; i < 8; i++) {
        int lin = tid + i * 256;
        int r = lin >> 4;
        int ch = lin & 15;
        int gr = row0 + r;
        if (gr >= NN) gr = NN - 1;
        float4 v = *(const float4*)(&g_H1h[(long)gr * 64 + ch * 4]);
        *(float4*)(As2 + r * A2STR + ch * 8) = v;
    }
    // Bs2: W2 [128,16] fp32 -> fp16, padded stride 24
#pragma unroll
    for (int i = 0; i < 8; i++) {
        int idx = tid + i * 256;
        int r = idx >> 4;
        int c = idx & 15;
        float v = W2[(long)rel * 2048 + r * 16 + c];
        Bs2[r * B2STR + c] = __float2half_rn(v);
    }
    __syncthreads();

    wmma::fragment<wmma::accumulator, 16, 16, 16, float> acc;
    wmma::fill_fragment(acc, 0.f);
#pragma unroll
    for (int ks = 0; ks < 8; ks++) {
        int k0 = ks * 16;
        wmma::fragment<wmma::matrix_a, 16, 16, 16, __half, wmma::row_major> af;
        wmma::fragment<wmma::matrix_b, 16, 16, 16, __half, wmma::row_major> bf;
        wmma::load_matrix_sync(af, As2 + (warp * 16) * A2STR + k0, A2STR);
        wmma::load_matrix_sync(bf, Bs2 + k0 * B2STR, B2STR);
        wmma::mma_sync(acc, af, bf, acc);
    }
    __syncthreads();   // done with As2; reuse as scratch

    float* scr = (float*)smraw2 + warp * 256;
    wmma::store_matrix_sync(scr, acc, 16, wmma::mem_row_major);
    __syncwarp();

    // z2 store
#pragma unroll
    for (int q = 0; q < 8; q++) {
        int idx = lane + q * 32;
        int rr = idx >> 4;
        int cc = idx & 15;
        int row = row0 + warp * 16 + rr;
        if (row < NN) g_Z2[rel][(long)row * 16 + cc] = scr[rr * 16 + cc];
    }
    // el2 / er2
    if (lane < 16) {
        int row = row0 + warp * 16 + lane;
        if (row < NN) {
            float el = 0.f;
            float er = 0.f;
#pragma unroll
            for (int j = 0; j < 16; j++) {
                float zv = scr[lane * 16 + j];
                el += zv * al2S[j];
                er += zv * ar2S[j];
            }
            g_EL2[rel][row] = el;
            g_ER2[rel][row] = er;
        }
    }
}

// ---------------- layer2 fused CSR aggregation (4 per half-warp) -------------
__global__ __launch_bounds__(256) void k_agg2csr(const float* __restrict__ b2,
                                                 float* __restrict__ out) {
    int w = (blockIdx.x * 256 + threadIdx.x) >> 5;
    if (w >= NN) return;
    int d = w;
    int lane = threadIdx.x & 31, hh = lane >> 4, c = lane & 15;
    float acc = 0.f;

#pragma unroll
    for (int rel = 0; rel < RR; rel++) {
        float er = g_ER2[rel][d];
        int idx = rel * NN + d;
        int base = g_off[idx], n = g_cnt[idx];
        float aR = 0.f, den = 0.f;
        int i = hh;
        for (; i + 6 < n; i += 8) {
            int s0 = g_csrc[base + i];
            int s1 = g_csrc[base + i + 2];
            int s2 = g_csrc[base + i + 4];
            int s3 = g_csrc[base + i + 6];
            float e0 = g_EL2[rel][s0];
            float e1 = g_EL2[rel][s1];
            float e2 = g_EL2[rel][s2];
            float e3 = g_EL2[rel][s3];
            float za = g_Z2[rel][s0 * 16 + c];
            float zb = g_Z2[rel][s1 * 16 + c];
            float zc = g_Z2[rel][s2 * 16 + c];
            float zd = g_Z2[rel][s3 * 16 + c];
            float p0 = lrexp(e0, er);
            float p1 = lrexp(e1, er);
            float p2 = lrexp(e2, er);
            float p3 = lrexp(e3, er);
            aR += p0 * za + p1 * zb + p2 * zc + p3 * zd;
            den += p0 + p1 + p2 + p3;
        }
        for (; i < n; i += 2) {
            int s = g_csrc[base + i];
            float p = lrexp(g_EL2[rel][s], er);
            aR += p * g_Z2[rel][s * 16 + c];
            den += p;
        }
        den += __shfl_xor_sync(0xffffffffu, den, 16);
        float rden = (n > 0) ? __frcp_rn(den) : 0.f;
        acc += aR * rden;
    }
    acc += __shfl_xor_sync(0xffffffffu, acc, 16);
    if (hh == 0) {
        float bs = b2[c] + b2[16 + c] + b2[32 + c];
        out[d * 16 + c] = (acc + bs) * (1.f / 3.f);
    }
}

// ---------------- launcher ----------------
extern "C" void kernel_launch(void* const* d_in, const int* in_sizes, int n_in,
                              void* d_out, int out_size) {
    const float* x   = (const float*)d_in[0];
    const int*   src = (const int*)d_in[1];
    const int*   dst = (const int*)d_in[2];
    const float* W1  = (const float*)d_in[3];
    const float* al1 = (const float*)d_in[4];
    const float* ar1 = (const float*)d_in[5];
    const float* b1  = (const float*)d_in[6];
    const float* W2  = (const float*)d_in[7];
    const float* al2 = (const float*)d_in[8];
    const float* ar2 = (const float*)d_in[9];
    const float* b2  = (const float*)d_in[10];
    float* out = (float*)d_out;

    k_zero_cnt<<<(TOT + 255) / 256, 256>>>();
    dim3 ge((EE + 255) / 256, RR);
    k_hist<<<ge, 256>>>(dst);
    k_scan1<<<SCAN_BLK, 256>>>();

    dim3 gm((NN + 127) / 128, 1, RR);
    k_gemm1_wmma<<<gm, 256>>>(x, W1, al1, ar1);   // launch index 3 (profiled)

    k_scan2<<<1, 512>>>();
    k_scan3<<<SCAN_BLK, 256>>>();
    k_scatter<<<ge, 256>>>(src, dst);

    k_agg1csr<<<(NN * 32 + 255) / 256, 256>>>(b1);

    k_gemm2_wmma<<<gm, 256>>>(W2, al2, ar2);
    k_agg2csr<<<(NN * 32 + 255) / 256, 256>>>(b2, out);
}

// round 11
// speedup vs baseline: 2.5221x; 1.0225x over previous
#include <cuda_runtime.h>
#include <cuda_fp16.h>
#include <mma.h>
#include <math.h>

using namespace nvcuda;

#define NN 100000
#define RR 3
#define EE 1600000
#define TOT (RR * NN)
#define SCAN_GRID 293

__device__ __align__(16) __half2 g_Z1h[RR][(long)NN * 64];
__device__ __align__(16) float g_EL1[RR][NN * 4];
__device__ __align__(16) float g_ER1[RR][NN * 4];
__device__ __align__(16) __half2 g_H1h[(long)NN * 64];
__device__ __align__(16) float g_Z2[RR][NN * 16];
__device__ __align__(16) float g_EL2[RR][NN];
__device__ __align__(16) float g_ER2[RR][NN];

__device__ int g_cnt[TOT];
__device__ int g_off[TOT];
__device__ int g_cur[TOT];
__device__ int g_grand;
__device__ int g_csrc[RR * EE];

struct __align__(8) h4 { __half2 a, b; };

__device__ __forceinline__ float lrexp(float a, float b) {
    float e = a + b;
    e = e > 0.f ? e : 0.2f * e;
    return __expf(e);
}

// ---------------- CSR build ----------------
__global__ void k_zero_cnt() {
    int i = blockIdx.x * 256 + threadIdx.x;
    if (i < TOT) g_cnt[i] = 0;
    if (i == 0) g_grand = 0;
}

__global__ __launch_bounds__(256) void k_hist(const int* __restrict__ dst) {
    int rel = blockIdx.y;
    long e = blockIdx.x * 256L + threadIdx.x;
    if (e >= EE) return;
    int d = dst[(long)rel * EE + e];
    atomicAdd(&g_cnt[rel * NN + d], 1);
}

// fused scan: block-local exclusive scan + atomic block base (offsets disjoint)
__global__ __launch_bounds__(256) void k_scanF() {
    __shared__ int ssum[256];
    __shared__ int sbase;
    int t = threadIdx.x;
    int base = blockIdx.x * 1024 + t * 4;
    int v0 = (base + 0 < TOT) ? g_cnt[base + 0] : 0;
    int v1 = (base + 1 < TOT) ? g_cnt[base + 1] : 0;
    int v2 = (base + 2 < TOT) ? g_cnt[base + 2] : 0;
    int v3 = (base + 3 < TOT) ? g_cnt[base + 3] : 0;
    int tsum = v0 + v1 + v2 + v3;
    ssum[t] = tsum;
    __syncthreads();
    for (int off = 1; off < 256; off <<= 1) {
        int xv = (t >= off) ? ssum[t - off] : 0;
        __syncthreads();
        ssum[t] += xv;
        __syncthreads();
    }
    if (t == 255) sbase = atomicAdd(&g_grand, ssum[255]);
    __syncthreads();
    int run = ssum[t] - tsum + sbase;
    if (base + 0 < TOT) { g_off[base + 0] = run; g_cur[base + 0] = run; }
    run += v0;
    if (base + 1 < TOT) { g_off[base + 1] = run; g_cur[base + 1] = run; }
    run += v1;
    if (base + 2 < TOT) { g_off[base + 2] = run; g_cur[base + 2] = run; }
    run += v2;
    if (base + 3 < TOT) { g_off[base + 3] = run; g_cur[base + 3] = run; }
}

__global__ __launch_bounds__(256) void k_scatter(const int* __restrict__ src,
                                                 const int* __restrict__ dst) {
    int rel = blockIdx.y;
    long e = blockIdx.x * 256L + threadIdx.x;
    if (e >= EE) return;
    int s = src[(long)rel * EE + e];
    int d = dst[(long)rel * EE + e];
    int pos = atomicAdd(&g_cur[rel * NN + d], 1);
    g_csrc[pos] = s;
}

// ------- layer1 GEMM, 3 relations fused per CTA, dynamic smem ---------------
// A (x tile, fp16, full K=128) loaded once; per-rel: B fill, MMA, epilogue.
// St (staging) reuses the B region. 8 warps = 4m x 2n.
#define FSTR 136
__global__ __launch_bounds__(256) void k_gemm1f(const float* __restrict__ x,
                                                const float* __restrict__ W1,
                                                const float* __restrict__ al1,
                                                const float* __restrict__ ar1) {
    extern __shared__ __align__(16) char dsm[];
    __half* As = (__half*)dsm;                  // 128*136 halves = 34816 B
    __half* Bs = (__half*)(dsm + 34816);        // 34816 B (also St)
    float* scratch = (float*)(dsm + 69632);     // 8 warps * 256 f = 8192 B
    __shared__ float alS[384];
    __shared__ float arS[384];
    int row0 = blockIdx.x * 128;
    int tid = threadIdx.x;
    int lane = tid & 31;
    int warp = tid >> 5;
    int mw = warp & 3;
    int nw = warp >> 2;

    if (tid < 128) {
#pragma unroll
        for (int r = 0; r < RR; r++) {
            alS[r * 128 + tid] = al1[r * 128 + tid];
            arS[r * 128 + tid] = ar1[r * 128 + tid];
        }
    }

    // A fill once: 128 rows x 128 cols fp32 -> fp16
#pragma unroll
    for (int i = 0; i < 16; i++) {
        int lin = tid + i * 256;
        int r = lin >> 5;
        int c4 = lin & 31;
        int gr = row0 + r;
        if (gr >= NN) gr = NN - 1;
        float4 v = *(const float4*)(x + (long)gr * 128 + c4 * 4);
        __half2* p = (__half2*)(As + r * FSTR + c4 * 4);
        p[0] = __floats2half2_rn(v.x, v.y);
        p[1] = __floats2half2_rn(v.z, v.w);
    }

    for (int rel = 0; rel < RR; rel++) {
        const float* Wp = W1 + (long)rel * 16384;
        // B fill: 128 k-rows x 128 n-cols fp32 -> fp16
#pragma unroll
        for (int i = 0; i < 16; i++) {
            int lin = tid + i * 256;
            int r = lin >> 5;
            int c4 = lin & 31;
            float4 v = *(const float4*)(Wp + (long)r * 128 + c4 * 4);
            __half2* p = (__half2*)(Bs + r * FSTR + c4 * 4);
            p[0] = __floats2half2_rn(v.x, v.y);
            p[1] = __floats2half2_rn(v.z, v.w);
        }
        __syncthreads();

        wmma::fragment<wmma::accumulator, 16, 16, 16, float> acc0[4];
        wmma::fragment<wmma::accumulator, 16, 16, 16, float> acc1[4];
#pragma unroll
        for (int nt = 0; nt < 4; nt++) {
            wmma::fill_fragment(acc0[nt], 0.f);
            wmma::fill_fragment(acc1[nt], 0.f);
        }
#pragma unroll
        for (int ks = 0; ks < 8; ks++) {
            int k0 = ks * 16;
            wmma::fragment<wmma::matrix_a, 16, 16, 16, __half, wmma::row_major> af0;
            wmma::fragment<wmma::matrix_a, 16, 16, 16, __half, wmma::row_major> af1;
            wmma::load_matrix_sync(af0, As + (mw * 32) * FSTR + k0, FSTR);
            wmma::load_matrix_sync(af1, As + (mw * 32 + 16) * FSTR + k0, FSTR);
#pragma unroll
            for (int nt = 0; nt < 4; nt++) {
                wmma::fragment<wmma::matrix_b, 16, 16, 16, __half, wmma::row_major> bf;
                wmma::load_matrix_sync(bf, Bs + k0 * FSTR + nw * 64 + nt * 16, FSTR);
                wmma::mma_sync(acc0[nt], af0, bf, acc0[nt]);
                wmma::mma_sync(acc1[nt], af1, bf, acc1[nt]);
            }
        }
        __syncthreads();   // done reading Bs; reuse as staging tile

        __half* St = Bs;
        float* myscr = scratch + warp * 256;
#pragma unroll
        for (int mt = 0; mt < 2; mt++) {
#pragma unroll
            for (int nt = 0; nt < 4; nt++) {
                if (mt == 0) {
                    wmma::store_matrix_sync(myscr, acc0[nt], 16, wmma::mem_row_major);
                } else {
                    wmma::store_matrix_sync(myscr, acc1[nt], 16, wmma::mem_row_major);
                }
                __syncwarp();
#pragma unroll
                for (int q = 0; q < 4; q++) {
                    int idx = lane + q * 32;
                    int rr = idx >> 3;
                    int cc = (idx & 7) * 2;
                    __half2 hv = __floats2half2_rn(myscr[rr * 16 + cc],
                                                   myscr[rr * 16 + cc + 1]);
                    int gr2 = mw * 32 + mt * 16 + rr;
                    int gc = nw * 64 + nt * 16 + cc;
                    *(__half2*)(St + gr2 * FSTR + gc) = hv;
                }
                __syncwarp();
            }
        }
        __syncthreads();

        // coalesced fp16 z store
#pragma unroll
        for (int i = 0; i < 8; i++) {
            int lin = tid + i * 256;
            int r = lin >> 4;
            int ch = lin & 15;
            int gr = row0 + r;
            if (gr < NN) {
                float4 v = *(const float4*)(St + r * FSTR + ch * 8);
                *(float4*)(&g_Z1h[rel][(long)gr * 64 + ch * 4]) = v;
            }
        }
        // el/er from staged z
#pragma unroll
        for (int pp = 0; pp < 2; pp++) {
            int idx = tid + pp * 256;
            int r = idx >> 2;
            int h = idx & 3;
            int gr = row0 + r;
            if (gr < NN) {
                const __half2* zp = (const __half2*)(St + r * FSTR + h * 32);
                const float* alp = alS + rel * 128 + h * 32;
                const float* arp = arS + rel * 128 + h * 32;
                float el = 0.f;
                float er = 0.f;
#pragma unroll
                for (int f = 0; f < 16; f++) {
                    float2 z2 = __half22float2(zp[f]);
                    el += z2.x * alp[2 * f] + z2.y * alp[2 * f + 1];
                    er += z2.x * arp[2 * f] + z2.y * arp[2 * f + 1];
                }
                g_EL1[rel][gr * 4 + h] = el;
                g_ER1[rel][gr * 4 + h] = er;
            }
        }
        __syncthreads();   // St region becomes Bs again next rel
    }
}

// ------- layer1 fused CSR aggregation: hoisted metadata, 8-way, fp16 out -----
__global__ __launch_bounds__(256) void k_agg1csr(const float* __restrict__ b1) {
    int w = (blockIdx.x * 256 + threadIdx.x) >> 5;
    if (w >= NN) return;
    int d = w;
    int lane = threadIdx.x & 31, h = lane >> 3;
    float acc0 = 0.f, acc1 = 0.f, acc2 = 0.f, acc3 = 0.f;

    int baseA[RR];
    int cntA[RR];
    float erv[RR];
#pragma unroll
    for (int rel = 0; rel < RR; rel++) {
        int idx = rel * NN + d;
        baseA[rel] = g_off[idx];
        cntA[rel] = g_cnt[idx];
        erv[rel] = g_ER1[rel][d * 4 + h];
    }

#pragma unroll
    for (int rel = 0; rel < RR; rel++) {
        float er = erv[rel];
        int base = baseA[rel], n = cntA[rel];
        float a0 = 0.f, a1 = 0.f, a2 = 0.f, a3 = 0.f, den = 0.f;
        int i = 0;
        for (; i + 8 <= n; i += 8) {
            int s0 = g_csrc[base + i];
            int s1 = g_csrc[base + i + 1];
            int s2 = g_csrc[base + i + 2];
            int s3 = g_csrc[base + i + 3];
            int s4 = g_csrc[base + i + 4];
            int s5 = g_csrc[base + i + 5];
            int s6 = g_csrc[base + i + 6];
            int s7 = g_csrc[base + i + 7];
            float el0 = g_EL1[rel][s0 * 4 + h];
            float el1 = g_EL1[rel][s1 * 4 + h];
            float el2 = g_EL1[rel][s2 * 4 + h];
            float el3 = g_EL1[rel][s3 * 4 + h];
            float el4 = g_EL1[rel][s4 * 4 + h];
            float el5 = g_EL1[rel][s5 * 4 + h];
            float el6 = g_EL1[rel][s6 * 4 + h];
            float el7 = g_EL1[rel][s7 * 4 + h];
            h4 z0 = *(const h4*)&g_Z1h[rel][(long)s0 * 64 + lane * 2];
            h4 z1 = *(const h4*)&g_Z1h[rel][(long)s1 * 64 + lane * 2];
            h4 z2 = *(const h4*)&g_Z1h[rel][(long)s2 * 64 + lane * 2];
            h4 z3 = *(const h4*)&g_Z1h[rel][(long)s3 * 64 + lane * 2];
            h4 z4 = *(const h4*)&g_Z1h[rel][(long)s4 * 64 + lane * 2];
            h4 z5 = *(const h4*)&g_Z1h[rel][(long)s5 * 64 + lane * 2];
            h4 z6 = *(const h4*)&g_Z1h[rel][(long)s6 * 64 + lane * 2];
            h4 z7 = *(const h4*)&g_Z1h[rel][(long)s7 * 64 + lane * 2];
            float p0 = lrexp(el0, er);
            float p1 = lrexp(el1, er);
            float p2 = lrexp(el2, er);
            float p3 = lrexp(el3, er);
            float p4 = lrexp(el4, er);
            float p5 = lrexp(el5, er);
            float p6 = lrexp(el6, er);
            float p7 = lrexp(el7, er);
            float2 q0 = __half22float2(z0.a), r0 = __half22float2(z0.b);
            float2 q1 = __half22float2(z1.a), r1 = __half22float2(z1.b);
            float2 q2 = __half22float2(z2.a), r2 = __half22float2(z2.b);
            float2 q3 = __half22float2(z3.a), r3 = __half22float2(z3.b);
            float2 q4 = __half22float2(z4.a), r4 = __half22float2(z4.b);
            float2 q5 = __half22float2(z5.a), r5 = __half22float2(z5.b);
            float2 q6 = __half22float2(z6.a), r6 = __half22float2(z6.b);
            float2 q7 = __half22float2(z7.a), r7 = __half22float2(z7.b);
            a0 += p0 * q0.x + p1 * q1.x + p2 * q2.x + p3 * q3.x
                + p4 * q4.x + p5 * q5.x + p6 * q6.x + p7 * q7.x;
            a1 += p0 * q0.y + p1 * q1.y + p2 * q2.y + p3 * q3.y
                + p4 * q4.y + p5 * q5.y + p6 * q6.y + p7 * q7.y;
            a2 += p0 * r0.x + p1 * r1.x + p2 * r2.x + p3 * r3.x
                + p4 * r4.x + p5 * r5.x + p6 * r6.x + p7 * r7.x;
            a3 += p0 * r0.y + p1 * r1.y + p2 * r2.y + p3 * r3.y
                + p4 * r4.y + p5 * r5.y + p6 * r6.y + p7 * r7.y;
            den += p0 + p1 + p2 + p3 + p4 + p5 + p6 + p7;
        }
        for (; i < n; i++) {
            int s = g_csrc[base + i];
            float p = lrexp(g_EL1[rel][s * 4 + h], er);
            h4 z = *(const h4*)&g_Z1h[rel][(long)s * 64 + lane * 2];
            float2 zlo = __half22float2(z.a), zhi = __half22float2(z.b);
            a0 += p * zlo.x; a1 += p * zlo.y; a2 += p * zhi.x; a3 += p * zhi.y;
            den += p;
        }
        float rden = (n > 0) ? __frcp_rn(den) : 0.f;
        acc0 += a0 * rden; acc1 += a1 * rden; acc2 += a2 * rden; acc3 += a3 * rden;
    }
    int c = lane * 4;
    float4 bA = *(const float4*)(b1 + c);
    float4 bB = *(const float4*)(b1 + 128 + c);
    float4 bC = *(const float4*)(b1 + 256 + c);
    float v0 = (acc0 + bA.x + bB.x + bC.x) * (1.f / 3.f);
    float v1 = (acc1 + bA.y + bB.y + bC.y) * (1.f / 3.f);
    float v2 = (acc2 + bA.z + bB.z + bC.z) * (1.f / 3.f);
    float v3 = (acc3 + bA.w + bB.w + bC.w) * (1.f / 3.f);
    v0 = v0 > 0.f ? v0 : expm1f(v0);
    v1 = v1 > 0.f ? v1 : expm1f(v1);
    v2 = v2 > 0.f ? v2 : expm1f(v2);
    v3 = v3 > 0.f ? v3 : expm1f(v3);
    h4 hv;
    hv.a = __floats2half2_rn(v0, v1);
    hv.b = __floats2half2_rn(v2, v3);
    *(h4*)(&g_H1h[(long)d * 64 + lane * 2]) = hv;
}

// ---------------- layer2 GEMM via wmma (fp16 H1h input) ----------------------
#define A2STR 136
#define B2STR 24
__global__ __launch_bounds__(256) void k_gemm2_wmma(const float* __restrict__ W2,
                                                    const float* __restrict__ al2,
                                                    const float* __restrict__ ar2) {
    __shared__ __align__(16) char smraw2[40960];
    __shared__ float al2S[16];
    __shared__ float ar2S[16];
    __half* As2 = (__half*)smraw2;
    __half* Bs2 = (__half*)(smraw2 + 34816);
    int rel = blockIdx.z;
    int row0 = blockIdx.x * 128;
    int tid = threadIdx.x;
    int lane = tid & 31;
    int warp = tid >> 5;

    if (tid < 16) {
        al2S[tid] = al2[rel * 16 + tid];
        ar2S[tid] = ar2[rel * 16 + tid];
    }

#pragma unroll
    for (int i = 0; i < 8; i++) {
        int lin = tid + i * 256;
        int r = lin >> 4;
        int ch = lin & 15;
        int gr = row0 + r;
        if (gr >= NN) gr = NN - 1;
        float4 v = *(const float4*)(&g_H1h[(long)gr * 64 + ch * 4]);
        *(float4*)(As2 + r * A2STR + ch * 8) = v;
    }
#pragma unroll
    for (int i = 0; i < 8; i++) {
        int idx = tid + i * 256;
        int r = idx >> 4;
        int c = idx & 15;
        float v = W2[(long)rel * 2048 + r * 16 + c];
        Bs2[r * B2STR + c] = __float2half_rn(v);
    }
    __syncthreads();

    wmma::fragment<wmma::accumulator, 16, 16, 16, float> acc;
    wmma::fill_fragment(acc, 0.f);
#pragma unroll
    for (int ks = 0; ks < 8; ks++) {
        int k0 = ks * 16;
        wmma::fragment<wmma::matrix_a, 16, 16, 16, __half, wmma::row_major> af;
        wmma::fragment<wmma::matrix_b, 16, 16, 16, __half, wmma::row_major> bf;
        wmma::load_matrix_sync(af, As2 + (warp * 16) * A2STR + k0, A2STR);
        wmma::load_matrix_sync(bf, Bs2 + k0 * B2STR, B2STR);
        wmma::mma_sync(acc, af, bf, acc);
    }
    __syncthreads();

    float* scr = (float*)smraw2 + warp * 256;
    wmma::store_matrix_sync(scr, acc, 16, wmma::mem_row_major);
    __syncwarp();

#pragma unroll
    for (int q = 0; q < 8; q++) {
        int idx = lane + q * 32;
        int rr = idx >> 4;
        int cc = idx & 15;
        int row = row0 + warp * 16 + rr;
        if (row < NN) g_Z2[rel][(long)row * 16 + cc] = scr[rr * 16 + cc];
    }
    if (lane < 16) {
        int row = row0 + warp * 16 + lane;
        if (row < NN) {
            float el = 0.f;
            float er = 0.f;
#pragma unroll
            for (int j = 0; j < 16; j++) {
                float zv = scr[lane * 16 + j];
                el += zv * al2S[j];
                er += zv * ar2S[j];
            }
            g_EL2[rel][row] = el;
            g_ER2[rel][row] = er;
        }
    }
}

// ---------------- layer2 fused CSR aggregation (4 per half-warp) -------------
__global__ __launch_bounds__(256) void k_agg2csr(const float* __restrict__ b2,
                                                 float* __restrict__ out) {
    int w = (blockIdx.x * 256 + threadIdx.x) >> 5;
    if (w >= NN) return;
    int d = w;
    int lane = threadIdx.x & 31, hh = lane >> 4, c = lane & 15;
    float acc = 0.f;

#pragma unroll
    for (int rel = 0; rel < RR; rel++) {
        float er = g_ER2[rel][d];
        int idx = rel * NN + d;
        int base = g_off[idx], n = g_cnt[idx];
        float aR = 0.f, den = 0.f;
        int i = hh;
        for (; i + 6 < n; i += 8) {
            int s0 = g_csrc[base + i];
            int s1 = g_csrc[base + i + 2];
            int s2 = g_csrc[base + i + 4];
            int s3 = g_csrc[base + i + 6];
            float e0 = g_EL2[rel][s0];
            float e1 = g_EL2[rel][s1];
            float e2 = g_EL2[rel][s2];
            float e3 = g_EL2[rel][s3];
            float za = g_Z2[rel][s0 * 16 + c];
            float zb = g_Z2[rel][s1 * 16 + c];
            float zc = g_Z2[rel][s2 * 16 + c];
            float zd = g_Z2[rel][s3 * 16 + c];
            float p0 = lrexp(e0, er);
            float p1 = lrexp(e1, er);
            float p2 = lrexp(e2, er);
            float p3 = lrexp(e3, er);
            aR += p0 * za + p1 * zb + p2 * zc + p3 * zd;
            den += p0 + p1 + p2 + p3;
        }
        for (; i < n; i += 2) {
            int s = g_csrc[base + i];
            float p = lrexp(g_EL2[rel][s], er);
            aR += p * g_Z2[rel][s * 16 + c];
            den += p;
        }
        den += __shfl_xor_sync(0xffffffffu, den, 16);
        float rden = (n > 0) ? __frcp_rn(den) : 0.f;
        acc += aR * rden;
    }
    acc += __shfl_xor_sync(0xffffffffu, acc, 16);
    if (hh == 0) {
        float bs = b2[c] + b2[16 + c] + b2[32 + c];
        out[d * 16 + c] = (acc + bs) * (1.f / 3.f);
    }
}

// ---------------- launcher ----------------
extern "C" void kernel_launch(void* const* d_in, const int* in_sizes, int n_in,
                              void* d_out, int out_size) {
    const float* x   = (const float*)d_in[0];
    const int*   src = (const int*)d_in[1];
    const int*   dst = (const int*)d_in[2];
    const float* W1  = (const float*)d_in[3];
    const float* al1 = (const float*)d_in[4];
    const float* ar1 = (const float*)d_in[5];
    const float* b1  = (const float*)d_in[6];
    const float* W2  = (const float*)d_in[7];
    const float* al2 = (const float*)d_in[8];
    const float* ar2 = (const float*)d_in[9];
    const float* b2  = (const float*)d_in[10];
    float* out = (float*)d_out;

    cudaFuncSetAttribute(k_gemm1f, cudaFuncAttributeMaxDynamicSharedMemorySize,
                         77824);

    k_zero_cnt<<<(TOT + 255) / 256, 256>>>();
    dim3 ge((EE + 255) / 256, RR);
    k_hist<<<ge, 256>>>(dst);
    k_scanF<<<SCAN_GRID, 256>>>();
    k_scatter<<<ge, 256>>>(src, dst);          // launch index 3 (profiled)

    k_gemm1f<<<(NN + 127) / 128, 256, 77824>>>(x, W1, al1, ar1);
    k_agg1csr<<<(NN * 32 + 255) / 256, 256>>>(b1);

    dim3 gm((NN + 127) / 128, 1, RR);
    k_gemm2_wmma<<<gm, 256>>>(W2, al2, ar2);
    k_agg2csr<<<(NN * 32 + 255) / 256, 256>>>(b2, out);
}